// round 10
// baseline (speedup 1.0000x reference)
#include <cuda_runtime.h>
#include <stdint.h>

#define Dm 256
#define Bm 16384
#define NSTEPS 5
#define Mrows 8
#define NW 8
#define LCAP 264

#define SIGNB 0x80000000
#define PADB  0x40000000
#define OFMASK 0x0003FC00   // idx<<10 (byte offset of W row) for idx<256

typedef unsigned long long u64;

// ---- f32x2 packed helpers (per-half IEEE rn => bit-identical to scalar) ----

static __device__ __forceinline__ u64 pack2(float a, float b) {
    u64 r; asm("mov.b64 %0, {%1, %2};" : "=l"(r) : "f"(a), "f"(b)); return r;
}
static __device__ __forceinline__ void unpack2(u64 v, float& a, float& b) {
    asm("mov.b64 {%0, %1}, %2;" : "=f"(a), "=f"(b) : "l"(v));
}
static __device__ __forceinline__ u64 bc(float c) { return pack2(c, c); }
static __device__ __forceinline__ u64 fma2(u64 a, u64 b, u64 c) {
    u64 r; asm("fma.rn.f32x2 %0, %1, %2, %3;" : "=l"(r) : "l"(a), "l"(b), "l"(c)); return r;
}
static __device__ __forceinline__ u64 mul2(u64 a, u64 b) {
    u64 r; asm("mul.rn.f32x2 %0, %1, %2;" : "=l"(r) : "l"(a), "l"(b)); return r;
}
static __device__ __forceinline__ u64 add2(u64 a, u64 b) {
    u64 r; asm("add.rn.f32x2 %0, %1, %2;" : "=l"(r) : "l"(a), "l"(b)); return r;
}

// ---- paired sigmoid: per-half bit-identical to the R6 scalar my_sigmoid ----
// (magic-number rint == rintf for |z| < 2^22; here |z| <= 116)

static __device__ __forceinline__ void sigmoid2(float t0, float t1,
                                                float& o0, float& o1) {
    float x0 = fmaxf(-fabsf(t0), -80.0f);
    float x1 = fmaxf(-fabsf(t1), -80.0f);
    u64 xx = pack2(x0, x1);
    u64 zz = mul2(xx, bc(1.4426950408889634f));
    u64 nn = add2(zz, bc(12582912.0f));
    nn = add2(nn, bc(-12582912.0f));                 // == rintf per half
    u64 rr_ = fma2(nn, bc(-0.693359375f), xx);
    rr_ = fma2(nn, bc(2.12194440054690583e-4f), rr_);
    u64 pp = bc(1.9841269841269841e-4f);
    pp = fma2(pp, rr_, bc(1.3888888888888889e-3f));
    pp = fma2(pp, rr_, bc(8.3333333333333333e-3f));
    pp = fma2(pp, rr_, bc(4.1666666666666664e-2f));
    pp = fma2(pp, rr_, bc(1.6666666666666666e-1f));
    pp = fma2(pp, rr_, bc(0.5f));
    pp = fma2(pp, rr_, bc(1.0f));
    pp = fma2(pp, rr_, bc(1.0f));
    float p0, p1, n0f, n1f;
    unpack2(pp, p0, p1);
    unpack2(nn, n0f, n1f);
    int n0 = (int)n0f, n1 = (int)n1f;
    float en0 = p0 * __int_as_float((127 + n0) << 23);
    float en1 = p1 * __int_as_float((127 + n1) << 23);
    float s0 = __fdiv_rn(en0, 1.0f + en0);
    float s1 = __fdiv_rn(en1, 1.0f + en1);
    o0 = (t0 > 0.0f) ? 1.0f - s0 : s0;
    o1 = (t1 > 0.0f) ? 1.0f - s1 : s1;
}

// ---- paired log: per-half bit-identical to the R6 scalar my_log ----

static __device__ __forceinline__ void log2pair(float v0, float v1,
                                                float& o0, float& o1) {
    int i0 = __float_as_int(v0), i1 = __float_as_int(v1);
    int e0 = (i0 - 0x3f3504f3) >> 23, e1 = (i1 - 0x3f3504f3) >> 23;
    float m0 = __int_as_float(i0 - (e0 << 23));
    float m1 = __int_as_float(i1 - (e1 << 23));
    u64 ff = add2(pack2(m0, m1), bc(-1.0f));
    u64 zz = mul2(ff, ff);
    u64 pp = bc(7.0376836292e-2f);
    pp = fma2(pp, ff, bc(-1.1514610310e-1f));
    pp = fma2(pp, ff, bc(1.1676998740e-1f));
    pp = fma2(pp, ff, bc(-1.2420140846e-1f));
    pp = fma2(pp, ff, bc(1.4249322787e-1f));
    pp = fma2(pp, ff, bc(-1.6668057665e-1f));
    pp = fma2(pp, ff, bc(2.0000714765e-1f));
    pp = fma2(pp, ff, bc(-2.4999993993e-1f));
    pp = fma2(pp, ff, bc(3.3333331174e-1f));
    u64 pz = mul2(pp, zz);
    u64 inner = fma2(bc(-0.5f), zz, ff);
    u64 rr_ = fma2(pz, ff, inner);
    u64 ef = pack2((float)e0, (float)e1);
    u64 out = fma2(ef, bc(0.693359375f),
                   fma2(ef, bc(-2.12194440054690583e-4f), rr_));
    unpack2(out, o0, o1);
}

// scalar log (accept path, 8 threads only) — same sequence as log2pair per lane
static __device__ __forceinline__ float my_log(float v) {
    int i = __float_as_int(v);
    int e = (i - 0x3f3504f3) >> 23;
    float m = __int_as_float(i - (e << 23));
    float f = m - 1.0f;
    float z = f * f;
    float p = 7.0376836292e-2f;
    p = fmaf(p, f, -1.1514610310e-1f);
    p = fmaf(p, f, 1.1676998740e-1f);
    p = fmaf(p, f, -1.2420140846e-1f);
    p = fmaf(p, f, 1.4249322787e-1f);
    p = fmaf(p, f, -1.6668057665e-1f);
    p = fmaf(p, f, 2.0000714765e-1f);
    p = fmaf(p, f, -2.4999993993e-1f);
    p = fmaf(p, f, 3.3333331174e-1f);
    float r = fmaf(p * z, f, fmaf(-0.5f, z, f));
    float ef = (float)e;
    return fmaf(ef, 0.693359375f, fmaf(ef, -2.12194440054690583e-4f, r));
}

static __device__ __forceinline__ float sxor(float w, int e) {
    return __int_as_float(__float_as_int(w) ^ (e & SIGNB));
}

// R6's proven gather loop: 4 LDG.128 in flight, XOR sign, FADD chain, exact tail.
static __device__ __forceinline__ float4 gather_row(
    const char* wbase, const int* fl, int cnt, float4 acc)
{
    const int4* fl4 = reinterpret_cast<const int4*>(fl);
    const int full = cnt & ~3;
    int4 en = fl4[0];
    for (int i = 0; i < full; i += 4) {
        int4 e = en;
        en = fl4[(i >> 2) + 1];
        float4 w0 = *reinterpret_cast<const float4*>(wbase + (e.x & OFMASK));
        float4 w1 = *reinterpret_cast<const float4*>(wbase + (e.y & OFMASK));
        float4 w2 = *reinterpret_cast<const float4*>(wbase + (e.z & OFMASK));
        float4 w3 = *reinterpret_cast<const float4*>(wbase + (e.w & OFMASK));
        acc.x += sxor(w0.x, e.x); acc.y += sxor(w0.y, e.x);
        acc.z += sxor(w0.z, e.x); acc.w += sxor(w0.w, e.x);
        acc.x += sxor(w1.x, e.y); acc.y += sxor(w1.y, e.y);
        acc.z += sxor(w1.z, e.y); acc.w += sxor(w1.w, e.y);
        acc.x += sxor(w2.x, e.z); acc.y += sxor(w2.y, e.z);
        acc.z += sxor(w2.z, e.z); acc.w += sxor(w2.w, e.z);
        acc.x += sxor(w3.x, e.w); acc.y += sxor(w3.y, e.w);
        acc.z += sxor(w3.z, e.w); acc.w += sxor(w3.w, e.w);
    }
    if (cnt & 3) {   // one padded tail group: fmaf(sv in {+1,-1,0}) rounds identically
        #pragma unroll
        for (int j = 0; j < 4; j++) {
            int e = fl[full + j];
            float sv = (e & PADB) ? 0.0f : ((e < 0) ? -1.0f : 1.0f);
            float4 w = *reinterpret_cast<const float4*>(wbase + (e & OFMASK));
            acc.x = fmaf(sv, w.x, acc.x);
            acc.y = fmaf(sv, w.y, acc.y);
            acc.z = fmaf(sv, w.z, acc.z);
            acc.w = fmaf(sv, w.w, acc.w);
        }
    }
    return acc;
}

// ---- fused sampler: one block = 8 chains (R6 structure + paired math) ----

__global__ void __launch_bounds__(256, 4)
els_kernel(const float* __restrict__ x_in, const float* __restrict__ xa_in,
           const float* __restrict__ Wm, const float* __restrict__ bv,
           const float* __restrict__ rr, const float* __restrict__ noise,
           const float* __restrict__ au, float* __restrict__ out)
{
    const int d = threadIdx.x;
    const int warp = d >> 5;
    const int lane = d & 31;
    const int rowBase = blockIdx.x * Mrows;

    __shared__ float   xh[Mrows * Dm];
    __shared__ unsigned posw[Mrows][NW];
    __shared__ unsigned negw[Mrows][NW];
    __shared__ int     flist[Mrows][LCAP];
    __shared__ int     fcnt[Mrows];
    __shared__ float   red[Mrows][NW];
    __shared__ float   accs[Mrows];
    __shared__ float   xdas[Mrows][Dm];
    __shared__ float   taccs[Mrows][Dm];
    __shared__ float   h2s[Mrows][Dm];

    const float bd = bv[d];
    float xa[Mrows];
    unsigned xmask = 0;

    #pragma unroll
    for (int m = 0; m < Mrows; m++) {
        float xv = __ldcs(&x_in[(size_t)(rowBase + m) * Dm + d]);
        xa[m] = __ldcs(&xa_in[(size_t)(rowBase + m) * Dm + d]);
        bool one = xv != 0.0f;
        if (one) xmask |= (1u << m);
        unsigned pb = __ballot_sync(0xffffffffu, one);
        if (lane == 0) { posw[m][warp] = pb; negw[m][warp] = 0u; }
    }
    if (lane == 0) {
        size_t base0 = (size_t)rowBase * Dm + (warp << 5);
        #pragma unroll
        for (int m = 0; m < Mrows; m++) {
            asm volatile("prefetch.global.L2 [%0];" :: "l"(rr + base0 + (size_t)m * Dm));
            asm volatile("prefetch.global.L2 [%0];" :: "l"(noise + base0 + (size_t)m * Dm));
        }
    }
    if (d == 0) {
        #pragma unroll
        for (int s = 0; s < NSTEPS; s++)
            asm volatile("prefetch.global.L2 [%0];" :: "l"(au + (size_t)s * Bm + rowBase));
    }
    __syncthreads();

    // ---- build init lists (64 threads; negw==0 -> pos only + pad) ----
    if (d < Mrows * NW) {
        int m = d >> 3, c = d & 7;
        int off = 0;
        #pragma unroll
        for (int c2 = 0; c2 < NW; c2++) {
            int cnt = __popc(posw[m][c2]);
            if (c2 < c) off += cnt;
        }
        int base = c * 32;
        unsigned pw = posw[m][c];
        while (pw) { int j = __ffs(pw) - 1; pw &= pw - 1; flist[m][off++] = (base + j) << 10; }
        if (c == NW - 1) {
            int padded = (off + 3) & ~3;
            for (int i = off; i < padded; i++) flist[m][i] = PADB;
            fcnt[m] = off;
        }
    }
    __syncthreads();

    // ---- init gather: h = sum_{e: x=1} W[e][:] (ascending e, bit-exact) ----
    {
        const int g  = d & 63;
        const int rp = d >> 6;
        const char* wbase = (const char*)Wm + g * 16;
        float4 Z = make_float4(0.0f, 0.0f, 0.0f, 0.0f);
        float4 A = gather_row(wbase, flist[rp], fcnt[rp], Z);
        float4 B = gather_row(wbase, flist[rp + 4], fcnt[rp + 4], Z);
        *reinterpret_cast<float4*>(&xh[rp * Dm + g * 4]) = A;
        *reinterpret_cast<float4*>(&xh[(rp + 4) * Dm + g * 4]) = B;
    }
    __syncthreads();

    for (int step = 0; step < NSTEPS; step++) {
        unsigned indmask = 0;

        // ---- stage 1: paired proposal + forward terms ----
        #pragma unroll
        for (int mm = 0; mm < Mrows; mm += 2) {
            const int m0 = mm, m1 = mm + 1;
            float rv0 = __ldcs(&rr[((size_t)(step * Bm + rowBase + m0)) * Dm + d]);
            float nv0 = __ldcs(&noise[((size_t)(step * Bm + rowBase + m0)) * Dm + d]);
            float rv1 = __ldcs(&rr[((size_t)(step * Bm + rowBase + m1)) * Dm + d]);
            float nv1 = __ldcs(&noise[((size_t)(step * Bm + rowBase + m1)) * Dm + d]);
            float hm0 = xh[m0 * Dm + d], hm1 = xh[m1 * Dm + d];
            float xf0 = ((xmask >> m0) & 1u) ? 1.0f : 0.0f;
            float xf1 = ((xmask >> m1) & 1u) ? 1.0f : 0.0f;
            float sgn0 = 1.0f - 2.0f * xf0, sgn1 = 1.0f - 2.0f * xf1;
            float ga0 = (xf0 - xa[m0]) * 1e-4f, ga1 = (xf1 - xa[m1]) * 1e-4f;
            float hb0 = hm0 + bd, hb1 = hm1 + bd;
            float gm0 = (hb0 * sgn0) * 0.5f - (ga0 * 0.5f) * sgn0;
            float gm1 = (hb1 * sgn1) * 0.5f - (ga1 * 0.5f) * sgn1;
            float fp0, fp1;
            sigmoid2(gm0 - 2.5f, gm1 - 2.5f, fp0, fp1);
            bool ind0 = rv0 < fp0, ind1 = rv1 < fp1;
            float inner0 = xa[m0] + 0.25f * ga0, inner1 = xa[m1] + 0.25f * ga1;
            float pn0 = __fmul_rn(0.70710678118654752f, nv0);
            float pn1 = __fmul_rn(0.70710678118654752f, nv1);
            float xdav0 = inner0 + pn0, xdav1 = inner1 + pn1;
            float la0 = (ind0 ? fp0 : 1.0f - fp0) + 1e-10f;
            float la1 = (ind1 ? fp1 : 1.0f - fp1) + 1e-10f;
            float lpf0, lpf1;
            log2pair(la0, la1, lpf0, lpf1);
            float e10 = (xf0 != 0.0f) ? fmaf(0.5f, hm0, bd) : 0.0f;
            float e11 = (xf1 != 0.0f) ? fmaf(0.5f, hm1, bd) : 0.0f;
            float dxa0 = xf0 - xa[m0], dxa1 = xf1 - xa[m1];
            float q10 = xdav0 - inner0, q11 = xdav1 - inner1;
            taccs[m0][d] = fmaf(dxa0 * dxa0, 5e-5f, q10 * q10) - lpf0 - e10;
            taccs[m1][d] = fmaf(dxa1 * dxa1, 5e-5f, q11 * q11) - lpf1 - e11;
            if (ind0) indmask |= (1u << m0);
            if (ind1) indmask |= (1u << m1);
            unsigned pb0 = __ballot_sync(0xffffffffu, ind0 && xf0 == 0.0f);
            unsigned nb0 = __ballot_sync(0xffffffffu, ind0 && xf0 != 0.0f);
            if (lane == 0) { posw[m0][warp] = pb0; negw[m0][warp] = nb0; }
            unsigned pb1 = __ballot_sync(0xffffffffu, ind1 && xf1 == 0.0f);
            unsigned nb1 = __ballot_sync(0xffffffffu, ind1 && xf1 != 0.0f);
            if (lane == 0) { posw[m1][warp] = pb1; negw[m1][warp] = nb1; }
            xdas[m0][d] = xdav0;
            xdas[m1][d] = xdav1;
        }
        __syncthreads();

        // ---- stage 1b: expand bitmasks into per-row packed flip lists ----
        if (d < Mrows * NW) {
            int m = d >> 3, c = d & 7;
            int off = 0;
            #pragma unroll
            for (int c2 = 0; c2 < NW; c2++) {
                int cnt = __popc(posw[m][c2]) + __popc(negw[m][c2]);
                if (c2 < c) off += cnt;
            }
            int base = c * 32;
            unsigned pw = posw[m][c];
            while (pw) { int j = __ffs(pw) - 1; pw &= pw - 1; flist[m][off++] = (base + j) << 10; }
            unsigned nw_ = negw[m][c];
            while (nw_) { int j = __ffs(nw_) - 1; nw_ &= nw_ - 1; flist[m][off++] = (int)(SIGNB | (unsigned)((base + j) << 10)); }
            if (c == NW - 1) {
                int padded = (off + 3) & ~3;
                for (int i = off; i < padded; i++) flist[m][i] = PADB;
                fcnt[m] = off;
            }
        }
        __syncthreads();

        // ---- stage 2a: per-row gathers (+ L2 prefetch of next step's streams) ----
        {
            if (lane == 0 && step + 1 < NSTEPS) {
                size_t basep = ((size_t)((step + 1) * Bm + rowBase)) * Dm + (warp << 5);
                #pragma unroll
                for (int m = 0; m < Mrows; m++) {
                    asm volatile("prefetch.global.L2 [%0];" :: "l"(rr + basep + (size_t)m * Dm));
                    asm volatile("prefetch.global.L2 [%0];" :: "l"(noise + basep + (size_t)m * Dm));
                }
            }
            const int g  = d & 63;
            const int rp = d >> 6;
            const char* wbase = (const char*)Wm + g * 16;
            float4 A = *reinterpret_cast<const float4*>(&xh[rp * Dm + g * 4]);
            float4 B = *reinterpret_cast<const float4*>(&xh[(rp + 4) * Dm + g * 4]);
            A = gather_row(wbase, flist[rp], fcnt[rp], A);
            B = gather_row(wbase, flist[rp + 4], fcnt[rp + 4], B);
            *reinterpret_cast<float4*>(&h2s[rp][g * 4]) = A;
            *reinterpret_cast<float4*>(&h2s[rp + 4][g * 4]) = B;
        }
        __syncthreads();

        // ---- stage 2b: paired reverse terms + per-row la reduce ----
        #pragma unroll
        for (int mm = 0; mm < Mrows; mm += 2) {
            const int m0 = mm, m1 = mm + 1;
            float acc0 = h2s[m0][d], acc1 = h2s[m1][d];
            float xdav0 = xdas[m0][d], xdav1 = xdas[m1][d];
            float xf0 = ((xmask >> m0) & 1u) ? 1.0f : 0.0f;
            float xf1 = ((xmask >> m1) & 1u) ? 1.0f : 0.0f;
            bool ind0 = (indmask >> m0) & 1u, ind1 = (indmask >> m1) & 1u;
            float xdv0 = ind0 ? 1.0f - xf0 : xf0;
            float xdv1 = ind1 ? 1.0f - xf1 : xf1;
            float sgn20 = 1.0f - 2.0f * xdv0, sgn21 = 1.0f - 2.0f * xdv1;
            float ga20 = (xdv0 - xdav0) * 1e-4f, ga21 = (xdv1 - xdav1) * 1e-4f;
            float hb20 = acc0 + bd, hb21 = acc1 + bd;
            float gm20 = (hb20 * sgn20) * 0.5f - (ga20 * 0.5f) * sgn20;
            float gm21 = (hb21 * sgn21) * 0.5f - (ga21 * 0.5f) * sgn21;
            float fp20, fp21;
            sigmoid2(gm20 - 2.5f, gm21 - 2.5f, fp20, fp21);
            float lb0 = (ind0 ? fp20 : 1.0f - fp20) + 1e-10f;
            float lb1 = (ind1 ? fp21 : 1.0f - fp21) + 1e-10f;
            float lpr0, lpr1;
            log2pair(lb0, lb1, lpr0, lpr1);
            float e20 = (xdv0 != 0.0f) ? fmaf(0.5f, acc0, bd) : 0.0f;
            float e21 = (xdv1 != 0.0f) ? fmaf(0.5f, acc1, bd) : 0.0f;
            float dxd0 = xdv0 - xdav0, dxd1 = xdv1 - xdav1;
            float inner20 = fmaf(0.25f, ga20, xdav0);
            float inner21 = fmaf(0.25f, ga21, xdav1);
            float q20 = xa[m0] - inner20, q21 = xa[m1] - inner21;
            float t0 = taccs[m0][d] + lpr0 + e20 - fmaf(dxd0 * dxd0, 5e-5f, q20 * q20);
            float t1 = taccs[m1][d] + lpr1 + e21 - fmaf(dxd1 * dxd1, 5e-5f, q21 * q21);

            t0 += __shfl_down_sync(0xffffffffu, t0, 16);
            t1 += __shfl_down_sync(0xffffffffu, t1, 16);
            t0 += __shfl_down_sync(0xffffffffu, t0, 8);
            t1 += __shfl_down_sync(0xffffffffu, t1, 8);
            t0 += __shfl_down_sync(0xffffffffu, t0, 4);
            t1 += __shfl_down_sync(0xffffffffu, t1, 4);
            t0 += __shfl_down_sync(0xffffffffu, t0, 2);
            t1 += __shfl_down_sync(0xffffffffu, t1, 2);
            t0 += __shfl_down_sync(0xffffffffu, t0, 1);
            t1 += __shfl_down_sync(0xffffffffu, t1, 1);
            if (lane == 0) { red[m0][warp] = t0; red[m1][warp] = t1; }
        }
        __syncthreads();

        // ---- MH accept per row ----
        if (d < Mrows) {
            float la = 0.0f;
            #pragma unroll
            for (int w2 = 0; w2 < NW; w2++) la += red[d][w2];
            float u = __ldcs(&au[step * Bm + rowBase + d]);
            float lu = (u > 0.0f) ? my_log(u) : -3.0e38f;
            accs[d] = (la > lu) ? 1.0f : 0.0f;
        }
        __syncthreads();

        // ---- commit (thread-private slots; next cross-thread read is barriered) ----
        #pragma unroll
        for (int m = 0; m < Mrows; m++) {
            if (accs[m] != 0.0f) {
                xa[m] = xdas[m][d];
                xh[m * Dm + d] = h2s[m][d];
                xmask ^= (indmask & (1u << m));
            }
        }
    }

    #pragma unroll
    for (int m = 0; m < Mrows; m++) {
        float xf = ((xmask >> m) & 1u) ? 1.0f : 0.0f;
        __stcs(&out[(size_t)(rowBase + m) * Dm + d], xf);
        __stcs(&out[(size_t)Bm * Dm + (size_t)(rowBase + m) * Dm + d], xa[m]);
    }
}

extern "C" void kernel_launch(void* const* d_in, const int* in_sizes, int n_in,
                              void* d_out, int out_size) {
    const float* x  = (const float*)d_in[0];
    const float* xa = (const float*)d_in[1];
    const float* W  = (const float*)d_in[2];
    const float* b  = (const float*)d_in[3];
    const float* rr = (const float*)d_in[4];
    const float* nz = (const float*)d_in[5];
    const float* au = (const float*)d_in[6];
    els_kernel<<<Bm / Mrows, 256>>>(x, xa, W, b, rr, nz, au, (float*)d_out);
}

// round 11
// speedup vs baseline: 1.0501x; 1.0501x over previous
#include <cuda_runtime.h>
#include <stdint.h>

#define Dm 256
#define Bm 16384
#define NSTEPS 5
#define Mrows 8
#define NW 8
#define LCAP 264

#define SIGNB 0x80000000
#define PADB  0x40000000
#define OFMASK 0x0003FC00   // idx<<10 (byte offset of W row) for idx<256

// ---- flag-independent fp32 exp/log/sigmoid (pure FMA; sigmoid keeps __fdiv_rn) ----

static __device__ __forceinline__ float my_exp(float x) {
    x = fmaxf(x, -80.0f);
    float z = x * 1.4426950408889634f;
    float n = rintf(z);
    float r = fmaf(n, -0.693359375f, x);
    r = fmaf(n, 2.12194440054690583e-4f, r);
    float p = 1.9841269841269841e-4f;
    p = fmaf(p, r, 1.3888888888888889e-3f);
    p = fmaf(p, r, 8.3333333333333333e-3f);
    p = fmaf(p, r, 4.1666666666666664e-2f);
    p = fmaf(p, r, 1.6666666666666666e-1f);
    p = fmaf(p, r, 0.5f);
    p = fmaf(p, r, 1.0f);
    p = fmaf(p, r, 1.0f);
    int ni = (int)n;
    return p * __int_as_float((127 + ni) << 23);
}

static __device__ __forceinline__ float my_log(float v) {
    int i = __float_as_int(v);
    int e = (i - 0x3f3504f3) >> 23;
    float m = __int_as_float(i - (e << 23));
    float f = m - 1.0f;
    float z = f * f;
    float p = 7.0376836292e-2f;
    p = fmaf(p, f, -1.1514610310e-1f);
    p = fmaf(p, f, 1.1676998740e-1f);
    p = fmaf(p, f, -1.2420140846e-1f);
    p = fmaf(p, f, 1.4249322787e-1f);
    p = fmaf(p, f, -1.6668057665e-1f);
    p = fmaf(p, f, 2.0000714765e-1f);
    p = fmaf(p, f, -2.4999993993e-1f);
    p = fmaf(p, f, 3.3333331174e-1f);
    float r = fmaf(p * z, f, fmaf(-0.5f, z, f));
    float ef = (float)e;
    return fmaf(ef, 0.693359375f, fmaf(ef, -2.12194440054690583e-4f, r));
}

static __device__ __forceinline__ float my_sigmoid(float t) {   // decision-critical: unchanged
    float en = my_exp(-fabsf(t));
    float s = __fdiv_rn(en, 1.0f + en);
    return (t > 0.0f) ? 1.0f - s : s;
}

static __device__ __forceinline__ float sxor(float w, int e) {  // w * sign(e) via bit xor
    return __int_as_float(__float_as_int(w) ^ (e & SIGNB));
}

// W row-segment load, pinned in L1 (evict_last): same value, better residency
static __device__ __forceinline__ float4 ldw(const char* p) {
    float4 w;
    asm("ld.global.nc.L1::evict_last.v4.f32 {%0,%1,%2,%3}, [%4];"
        : "=f"(w.x), "=f"(w.y), "=f"(w.z), "=f"(w.w) : "l"(p));
    return w;
}

// R6's proven gather loop: 4 LDG.128 in flight, XOR sign, FADD chain, exact tail.
static __device__ __forceinline__ float4 gather_row(
    const char* wbase, const int* fl, int cnt, float4 acc)
{
    const int4* fl4 = reinterpret_cast<const int4*>(fl);
    const int full = cnt & ~3;
    int4 en = fl4[0];
    for (int i = 0; i < full; i += 4) {
        int4 e = en;
        en = fl4[(i >> 2) + 1];
        float4 w0 = ldw(wbase + (e.x & OFMASK));
        float4 w1 = ldw(wbase + (e.y & OFMASK));
        float4 w2 = ldw(wbase + (e.z & OFMASK));
        float4 w3 = ldw(wbase + (e.w & OFMASK));
        acc.x += sxor(w0.x, e.x); acc.y += sxor(w0.y, e.x);
        acc.z += sxor(w0.z, e.x); acc.w += sxor(w0.w, e.x);
        acc.x += sxor(w1.x, e.y); acc.y += sxor(w1.y, e.y);
        acc.z += sxor(w1.z, e.y); acc.w += sxor(w1.w, e.y);
        acc.x += sxor(w2.x, e.z); acc.y += sxor(w2.y, e.z);
        acc.z += sxor(w2.z, e.z); acc.w += sxor(w2.w, e.z);
        acc.x += sxor(w3.x, e.w); acc.y += sxor(w3.y, e.w);
        acc.z += sxor(w3.z, e.w); acc.w += sxor(w3.w, e.w);
    }
    if (cnt & 3) {   // one padded tail group: fmaf(sv in {+1,-1,0}) rounds identically
        #pragma unroll
        for (int j = 0; j < 4; j++) {
            int e = fl[full + j];
            float sv = (e & PADB) ? 0.0f : ((e < 0) ? -1.0f : 1.0f);
            float4 w = ldw(wbase + (e & OFMASK));
            acc.x = fmaf(sv, w.x, acc.x);
            acc.y = fmaf(sv, w.y, acc.y);
            acc.z = fmaf(sv, w.z, acc.z);
            acc.w = fmaf(sv, w.w, acc.w);
        }
    }
    return acc;
}

// ---- fused sampler: one block = 8 chains (exact R6 structure) ----

__global__ void __launch_bounds__(256, 4)
els_kernel(const float* __restrict__ x_in, const float* __restrict__ xa_in,
           const float* __restrict__ Wm, const float* __restrict__ bv,
           const float* __restrict__ rr, const float* __restrict__ noise,
           const float* __restrict__ au, float* __restrict__ out)
{
    const int d = threadIdx.x;
    const int warp = d >> 5;
    const int lane = d & 31;
    const int rowBase = blockIdx.x * Mrows;

    __shared__ float   xh[Mrows * Dm];         // h state, [m*256 + d]
    __shared__ unsigned posw[Mrows][NW];
    __shared__ unsigned negw[Mrows][NW];
    __shared__ int     flist[Mrows][LCAP];     // packed: sign | (idx<<10); PADB = pad
    __shared__ int     fcnt[Mrows];            // exact count
    __shared__ float   red[Mrows][NW];
    __shared__ float   accs[Mrows];
    __shared__ float   xdas[Mrows][Dm];
    __shared__ float   taccs[Mrows][Dm];
    __shared__ float   h2s[Mrows][Dm];

    const float bd = bv[d];
    float xa[Mrows];
    unsigned xmask = 0;

    // ---- load x/xa; ballot x-bits into posw (init "flip list" = ones of x) ----
    #pragma unroll
    for (int m = 0; m < Mrows; m++) {
        float xv = __ldcs(&x_in[(size_t)(rowBase + m) * Dm + d]);
        xa[m] = __ldcs(&xa_in[(size_t)(rowBase + m) * Dm + d]);
        bool one = xv != 0.0f;
        if (one) xmask |= (1u << m);
        unsigned pb = __ballot_sync(0xffffffffu, one);
        if (lane == 0) { posw[m][warp] = pb; negw[m][warp] = 0u; }
    }
    // prefetch step-0 rr/noise lines + au lines into L2 while init runs
    if (lane == 0) {
        size_t base0 = (size_t)rowBase * Dm + (warp << 5);
        #pragma unroll
        for (int m = 0; m < Mrows; m++) {
            asm volatile("prefetch.global.L2 [%0];" :: "l"(rr + base0 + (size_t)m * Dm));
            asm volatile("prefetch.global.L2 [%0];" :: "l"(noise + base0 + (size_t)m * Dm));
        }
    }
    if (d == 0) {
        #pragma unroll
        for (int s = 0; s < NSTEPS; s++)
            asm volatile("prefetch.global.L2 [%0];" :: "l"(au + (size_t)s * Bm + rowBase));
    }
    __syncthreads();

    // ---- build init lists (64 threads; negw==0 -> pos only + pad) ----
    if (d < Mrows * NW) {
        int m = d >> 3, c = d & 7;
        int off = 0;
        #pragma unroll
        for (int c2 = 0; c2 < NW; c2++) {
            int cnt = __popc(posw[m][c2]);
            if (c2 < c) off += cnt;
        }
        int base = c * 32;
        unsigned pw = posw[m][c];
        while (pw) { int j = __ffs(pw) - 1; pw &= pw - 1; flist[m][off++] = (base + j) << 10; }
        if (c == NW - 1) {
            int padded = (off + 3) & ~3;
            for (int i = off; i < padded; i++) flist[m][i] = PADB;
            fcnt[m] = off;
        }
    }
    __syncthreads();

    // ---- init gather: h = sum_{e: x=1} W[e][:]  (ascending e, bit-exact) ----
    {
        const int g  = d & 63;
        const int rp = d >> 6;
        const char* wbase = (const char*)Wm + g * 16;
        float4 Z = make_float4(0.0f, 0.0f, 0.0f, 0.0f);
        float4 A = gather_row(wbase, flist[rp], fcnt[rp], Z);
        float4 B = gather_row(wbase, flist[rp + 4], fcnt[rp + 4], Z);
        *reinterpret_cast<float4*>(&xh[rp * Dm + g * 4]) = A;
        *reinterpret_cast<float4*>(&xh[(rp + 4) * Dm + g * 4]) = B;
    }
    __syncthreads();

    for (int step = 0; step < NSTEPS; step++) {
        unsigned indmask = 0;

        // ---- stage 1: propose flips, forward log-prob terms ----
        #pragma unroll
        for (int m = 0; m < Mrows; m++) {
            float rv  = __ldcs(&rr[((size_t)(step * Bm + rowBase + m)) * Dm + d]);
            float nv  = __ldcs(&noise[((size_t)(step * Bm + rowBase + m)) * Dm + d]);
            float hm  = xh[m * Dm + d];
            float xf  = ((xmask >> m) & 1u) ? 1.0f : 0.0f;
            float sgn = 1.0f - 2.0f * xf;                    // -(2x-1)
            float ga  = (xf - xa[m]) * 1e-4f;                // (x - xa)/ETA
            float hb  = hm + bd;
            float gm  = (hb * sgn) * 0.5f - (ga * 0.5f) * sgn;
            float fp  = my_sigmoid(gm - 2.5f);
            bool ind  = rv < fp;
            float inner = xa[m] + 0.25f * ga;
            float pn  = __fmul_rn(0.70710678118654752f, nv);
            float xdav = inner + pn;
            float lpf = my_log((ind ? fp : 1.0f - fp) + 1e-10f);
            float e1  = (xf != 0.0f) ? fmaf(0.5f, hm, bd) : 0.0f;  // x*(0.5h+b)
            float dxa = xf - xa[m];
            float q1  = xdav - inner;
            taccs[m][d] = fmaf(dxa * dxa, 5e-5f, q1 * q1) - lpf - e1;
            if (ind) indmask |= (1u << m);
            unsigned pb = __ballot_sync(0xffffffffu, ind && xf == 0.0f);
            unsigned nb = __ballot_sync(0xffffffffu, ind && xf != 0.0f);
            if (lane == 0) { posw[m][warp] = pb; negw[m][warp] = nb; }
            xdas[m][d] = xdav;
        }
        __syncthreads();

        // ---- stage 1b: expand bitmasks into per-row packed flip lists ----
        // Order per row: chunk 0..7, pos asc then neg asc (bit-identical h2 order).
        if (d < Mrows * NW) {
            int m = d >> 3, c = d & 7;
            int off = 0;
            #pragma unroll
            for (int c2 = 0; c2 < NW; c2++) {
                int cnt = __popc(posw[m][c2]) + __popc(negw[m][c2]);
                if (c2 < c) off += cnt;
            }
            int base = c * 32;
            unsigned pw = posw[m][c];
            while (pw) { int j = __ffs(pw) - 1; pw &= pw - 1; flist[m][off++] = (base + j) << 10; }
            unsigned nw_ = negw[m][c];
            while (nw_) { int j = __ffs(nw_) - 1; nw_ &= nw_ - 1; flist[m][off++] = (int)(SIGNB | (unsigned)((base + j) << 10)); }
            if (c == NW - 1) {
                int padded = (off + 3) & ~3;
                for (int i = off; i < padded; i++) flist[m][i] = PADB;
                fcnt[m] = off;
            }
        }
        __syncthreads();

        // ---- stage 2a: per-row gathers (+ L2 prefetch of next step's streams) ----
        {
            if (lane == 0 && step + 1 < NSTEPS) {
                size_t basep = ((size_t)((step + 1) * Bm + rowBase)) * Dm + (warp << 5);
                #pragma unroll
                for (int m = 0; m < Mrows; m++) {
                    asm volatile("prefetch.global.L2 [%0];" :: "l"(rr + basep + (size_t)m * Dm));
                    asm volatile("prefetch.global.L2 [%0];" :: "l"(noise + basep + (size_t)m * Dm));
                }
            }
            const int g  = d & 63;
            const int rp = d >> 6;
            const char* wbase = (const char*)Wm + g * 16;
            float4 A = *reinterpret_cast<const float4*>(&xh[rp * Dm + g * 4]);
            float4 B = *reinterpret_cast<const float4*>(&xh[(rp + 4) * Dm + g * 4]);
            A = gather_row(wbase, flist[rp], fcnt[rp], A);
            B = gather_row(wbase, flist[rp + 4], fcnt[rp + 4], B);
            *reinterpret_cast<float4*>(&h2s[rp][g * 4]) = A;
            *reinterpret_cast<float4*>(&h2s[rp + 4][g * 4]) = B;
        }
        __syncthreads();

        // ---- stage 2b: reverse terms + per-row la reduce (owner thread d) ----
        #pragma unroll
        for (int m = 0; m < Mrows; m++) {
            float acc  = h2s[m][d];
            float xdav = xdas[m][d];
            float xf   = ((xmask >> m) & 1u) ? 1.0f : 0.0f;
            bool  ind  = (indmask >> m) & 1u;
            float xdv  = ind ? 1.0f - xf : xf;
            float sgn2 = 1.0f - 2.0f * xdv;
            float ga2  = (xdv - xdav) * 1e-4f;
            float hb2  = acc + bd;
            float gm2  = (hb2 * sgn2) * 0.5f - (ga2 * 0.5f) * sgn2;
            float fp2  = my_sigmoid(gm2 - 2.5f);
            float lpr  = my_log((ind ? fp2 : 1.0f - fp2) + 1e-10f);
            float e2   = (xdv != 0.0f) ? fmaf(0.5f, acc, bd) : 0.0f;
            float dxd  = xdv - xdav;
            float inner2 = fmaf(0.25f, ga2, xdav);
            float q2   = xa[m] - inner2;
            float t = taccs[m][d] + lpr + e2 - fmaf(dxd * dxd, 5e-5f, q2 * q2);

            t += __shfl_down_sync(0xffffffffu, t, 16);
            t += __shfl_down_sync(0xffffffffu, t, 8);
            t += __shfl_down_sync(0xffffffffu, t, 4);
            t += __shfl_down_sync(0xffffffffu, t, 2);
            t += __shfl_down_sync(0xffffffffu, t, 1);
            if (lane == 0) red[m][warp] = t;
        }
        __syncthreads();

        // ---- MH accept per row ----
        if (d < Mrows) {
            float la = 0.0f;
            #pragma unroll
            for (int w2 = 0; w2 < NW; w2++) la += red[d][w2];
            float u = __ldcs(&au[step * Bm + rowBase + d]);
            float lu = (u > 0.0f) ? my_log(u) : -3.0e38f;
            accs[d] = (la > lu) ? 1.0f : 0.0f;
        }
        __syncthreads();

        // ---- commit (thread-private slots only; next barrier is after stage 1) ----
        #pragma unroll
        for (int m = 0; m < Mrows; m++) {
            if (accs[m] != 0.0f) {
                xa[m] = xdas[m][d];
                xh[m * Dm + d] = h2s[m][d];
                xmask ^= (indmask & (1u << m));
            }
        }
    }

    #pragma unroll
    for (int m = 0; m < Mrows; m++) {
        float xf = ((xmask >> m) & 1u) ? 1.0f : 0.0f;
        __stcs(&out[(size_t)(rowBase + m) * Dm + d], xf);
        __stcs(&out[(size_t)Bm * Dm + (size_t)(rowBase + m) * Dm + d], xa[m]);
    }
}

extern "C" void kernel_launch(void* const* d_in, const int* in_sizes, int n_in,
                              void* d_out, int out_size) {
    const float* x  = (const float*)d_in[0];
    const float* xa = (const float*)d_in[1];
    const float* W  = (const float*)d_in[2];
    const float* b  = (const float*)d_in[3];
    const float* rr = (const float*)d_in[4];
    const float* nz = (const float*)d_in[5];
    const float* au = (const float*)d_in[6];
    els_kernel<<<Bm / Mrows, 256>>>(x, xa, W, b, rr, nz, au, (float*)d_out);
}

// round 12
// speedup vs baseline: 1.1307x; 1.0767x over previous
#include <cuda_runtime.h>
#include <stdint.h>

#define Dm 256
#define Bm 16384
#define NSTEPS 5
#define Mrows 8
#define NW 8
#define LCAP 264

#define SIGNB 0x80000000
#define PADB  0x40000000
#define OFMASK 0x0003FC00   // idx<<10 (byte offset of W row) for idx<256

// ---- flag-independent fp32 exp/log/sigmoid (pure FMA; sigmoid keeps __fdiv_rn) ----

static __device__ __forceinline__ float my_exp(float x) {
    x = fmaxf(x, -80.0f);
    float z = x * 1.4426950408889634f;
    float n = rintf(z);
    float r = fmaf(n, -0.693359375f, x);
    r = fmaf(n, 2.12194440054690583e-4f, r);
    float p = 1.9841269841269841e-4f;
    p = fmaf(p, r, 1.3888888888888889e-3f);
    p = fmaf(p, r, 8.3333333333333333e-3f);
    p = fmaf(p, r, 4.1666666666666664e-2f);
    p = fmaf(p, r, 1.6666666666666666e-1f);
    p = fmaf(p, r, 0.5f);
    p = fmaf(p, r, 1.0f);
    p = fmaf(p, r, 1.0f);
    int ni = (int)n;
    return p * __int_as_float((127 + ni) << 23);
}

static __device__ __forceinline__ float my_log(float v) {
    int i = __float_as_int(v);
    int e = (i - 0x3f3504f3) >> 23;
    float m = __int_as_float(i - (e << 23));
    float f = m - 1.0f;
    float z = f * f;
    float p = 7.0376836292e-2f;
    p = fmaf(p, f, -1.1514610310e-1f);
    p = fmaf(p, f, 1.1676998740e-1f);
    p = fmaf(p, f, -1.2420140846e-1f);
    p = fmaf(p, f, 1.4249322787e-1f);
    p = fmaf(p, f, -1.6668057665e-1f);
    p = fmaf(p, f, 2.0000714765e-1f);
    p = fmaf(p, f, -2.4999993993e-1f);
    p = fmaf(p, f, 3.3333331174e-1f);
    float r = fmaf(p * z, f, fmaf(-0.5f, z, f));
    float ef = (float)e;
    return fmaf(ef, 0.693359375f, fmaf(ef, -2.12194440054690583e-4f, r));
}

static __device__ __forceinline__ float my_sigmoid(float t) {   // decision-critical: unchanged
    float en = my_exp(-fabsf(t));
    float s = __fdiv_rn(en, 1.0f + en);
    return (t > 0.0f) ? 1.0f - s : s;
}

static __device__ __forceinline__ float sxor(float w, int e) {  // w * sign(e) via bit xor
    return __int_as_float(__float_as_int(w) ^ (e & SIGNB));
}

// ---- fused sampler: one block = 8 chains; thread d owns dim d for math,
// ---- gathers re-map to (64 dim-quads x 4 row-pairs) with LDG.128 ----

__global__ void __launch_bounds__(256, 4)
els_kernel(const float* __restrict__ x_in, const float* __restrict__ xa_in,
           const float* __restrict__ Wm, const float* __restrict__ bv,
           const float* __restrict__ rr, const float* __restrict__ noise,
           const float* __restrict__ au, float* __restrict__ out)
{
    const int d = threadIdx.x;
    const int warp = d >> 5;
    const int lane = d & 31;
    const int rowBase = blockIdx.x * Mrows;

    __shared__ float   xh[Mrows * Dm];         // h state, [m*256 + d]
    __shared__ unsigned posw[Mrows][NW];
    __shared__ unsigned negw[Mrows][NW];
    __shared__ int     flist[Mrows][LCAP];     // packed: sign | (idx<<10); PADB = pad
    __shared__ int     fcnt[Mrows];            // exact count
    __shared__ float   red[Mrows][NW];
    __shared__ float   accs[Mrows];
    __shared__ float   xdas[Mrows][Dm];
    __shared__ float   taccs[Mrows][Dm];
    __shared__ float   h2s[Mrows][Dm];

    const float bd = bv[d];
    float xa[Mrows];
    unsigned xmask = 0;

    // ---- load x/xa; ballot x-bits into posw (init "flip list" = ones of x) ----
    #pragma unroll
    for (int m = 0; m < Mrows; m++) {
        float xv = __ldcs(&x_in[(size_t)(rowBase + m) * Dm + d]);
        xa[m] = __ldcs(&xa_in[(size_t)(rowBase + m) * Dm + d]);
        bool one = xv != 0.0f;
        if (one) xmask |= (1u << m);
        unsigned pb = __ballot_sync(0xffffffffu, one);
        if (lane == 0) { posw[m][warp] = pb; negw[m][warp] = 0u; }
    }
    // prefetch step-0 rr/noise lines + au lines into L2 while init runs
    if (lane == 0) {
        size_t base0 = (size_t)rowBase * Dm + (warp << 5);
        #pragma unroll
        for (int m = 0; m < Mrows; m++) {
            asm volatile("prefetch.global.L2 [%0];" :: "l"(rr + base0 + (size_t)m * Dm));
            asm volatile("prefetch.global.L2 [%0];" :: "l"(noise + base0 + (size_t)m * Dm));
        }
    }
    if (d == 0) {
        #pragma unroll
        for (int s = 0; s < NSTEPS; s++)
            asm volatile("prefetch.global.L2 [%0];" :: "l"(au + (size_t)s * Bm + rowBase));
    }
    __syncthreads();

    // ---- build init lists (64 threads; negw==0 -> pos only + pad) ----
    if (d < Mrows * NW) {
        int m = d >> 3, c = d & 7;
        int off = 0;
        #pragma unroll
        for (int c2 = 0; c2 < NW; c2++) {
            int cnt = __popc(posw[m][c2]);
            if (c2 < c) off += cnt;
        }
        int base = c * 32;
        unsigned pw = posw[m][c];
        while (pw) { int j = __ffs(pw) - 1; pw &= pw - 1; flist[m][off++] = (base + j) << 10; }
        if (c == NW - 1) {
            int padded = (off + 3) & ~3;
            for (int i = off; i < padded; i++) flist[m][i] = PADB;
            fcnt[m] = off;
        }
    }
    __syncthreads();

    // ---- init gather: h = sum_{e: x=1} W[e][:]  (ascending e, bit-exact) ----
    {
        const int g  = d & 63;
        const int rp = d >> 6;
        const char* wbase = (const char*)Wm + g * 16;
        #pragma unroll
        for (int t = 0; t < 2; t++) {
            const int m = rp + t * 4;
            const int cnt  = fcnt[m];
            const int full = cnt & ~3;
            const int* fl = flist[m];
            const int4* fl4 = reinterpret_cast<const int4*>(fl);
            float4 acc = make_float4(0.0f, 0.0f, 0.0f, 0.0f);
            int4 en = fl4[0];
            #pragma unroll 2
            for (int i = 0; i < full; i += 4) {
                int4 e = en;
                en = fl4[(i >> 2) + 1];
                float4 w0 = *reinterpret_cast<const float4*>(wbase + (e.x & OFMASK));
                float4 w1 = *reinterpret_cast<const float4*>(wbase + (e.y & OFMASK));
                float4 w2 = *reinterpret_cast<const float4*>(wbase + (e.z & OFMASK));
                float4 w3 = *reinterpret_cast<const float4*>(wbase + (e.w & OFMASK));
                acc.x += w0.x; acc.y += w0.y; acc.z += w0.z; acc.w += w0.w;
                acc.x += w1.x; acc.y += w1.y; acc.z += w1.z; acc.w += w1.w;
                acc.x += w2.x; acc.y += w2.y; acc.z += w2.z; acc.w += w2.w;
                acc.x += w3.x; acc.y += w3.y; acc.z += w3.z; acc.w += w3.w;
            }
            if (cnt & 3) {
                #pragma unroll
                for (int j = 0; j < 4; j++) {
                    int e = fl[full + j];
                    float sv = (e & PADB) ? 0.0f : 1.0f;
                    float4 w = *reinterpret_cast<const float4*>(wbase + (e & OFMASK));
                    acc.x = fmaf(sv, w.x, acc.x);
                    acc.y = fmaf(sv, w.y, acc.y);
                    acc.z = fmaf(sv, w.z, acc.z);
                    acc.w = fmaf(sv, w.w, acc.w);
                }
            }
            *reinterpret_cast<float4*>(&xh[m * Dm + g * 4]) = acc;
        }
    }
    __syncthreads();

    for (int step = 0; step < NSTEPS; step++) {
        unsigned indmask = 0;

        // ---- stage 1: propose flips, forward log-prob terms ----
        #pragma unroll
        for (int m = 0; m < Mrows; m++) {
            float rv  = __ldcs(&rr[((size_t)(step * Bm + rowBase + m)) * Dm + d]);
            float nv  = __ldcs(&noise[((size_t)(step * Bm + rowBase + m)) * Dm + d]);
            float hm  = xh[m * Dm + d];
            float xf  = ((xmask >> m) & 1u) ? 1.0f : 0.0f;
            float sgn = 1.0f - 2.0f * xf;                    // -(2x-1)
            float ga  = (xf - xa[m]) * 1e-4f;                // (x - xa)/ETA
            float hb  = hm + bd;
            float gm  = (hb * sgn) * 0.5f - (ga * 0.5f) * sgn;
            float fp  = my_sigmoid(gm - 2.5f);
            bool ind  = rv < fp;
            float inner = xa[m] + 0.25f * ga;
            float pn  = __fmul_rn(0.70710678118654752f, nv);
            float xdav = inner + pn;
            float lpf = my_log((ind ? fp : 1.0f - fp) + 1e-10f);
            float e1  = (xf != 0.0f) ? fmaf(0.5f, hm, bd) : 0.0f;  // x*(0.5h+b)
            float dxa = xf - xa[m];
            float q1  = xdav - inner;
            taccs[m][d] = fmaf(dxa * dxa, 5e-5f, q1 * q1) - lpf - e1;
            if (ind) indmask |= (1u << m);
            unsigned pb = __ballot_sync(0xffffffffu, ind && xf == 0.0f);
            unsigned nb = __ballot_sync(0xffffffffu, ind && xf != 0.0f);
            if (lane == 0) { posw[m][warp] = pb; negw[m][warp] = nb; }
            xdas[m][d] = xdav;
        }
        __syncthreads();

        // ---- stage 1b: expand bitmasks into per-row packed flip lists ----
        // Order per row: chunk 0..7, pos asc then neg asc (bit-identical h2 order).
        if (d < Mrows * NW) {
            int m = d >> 3, c = d & 7;
            int off = 0;
            #pragma unroll
            for (int c2 = 0; c2 < NW; c2++) {
                int cnt = __popc(posw[m][c2]) + __popc(negw[m][c2]);
                if (c2 < c) off += cnt;
            }
            int base = c * 32;
            unsigned pw = posw[m][c];
            while (pw) { int j = __ffs(pw) - 1; pw &= pw - 1; flist[m][off++] = (base + j) << 10; }
            unsigned nw_ = negw[m][c];
            while (nw_) { int j = __ffs(nw_) - 1; nw_ &= nw_ - 1; flist[m][off++] = (int)(SIGNB | (unsigned)((base + j) << 10)); }
            if (c == NW - 1) {
                int padded = (off + 3) & ~3;
                for (int i = off; i < padded; i++) flist[m][i] = PADB;
                fcnt[m] = off;
            }
        }
        __syncthreads();

        // ---- stage 2a: per-row gathers (+ L2 prefetch of next step's streams) ----
        {
            if (lane == 0 && step + 1 < NSTEPS) {
                size_t basep = ((size_t)((step + 1) * Bm + rowBase)) * Dm + (warp << 5);
                #pragma unroll
                for (int m = 0; m < Mrows; m++) {
                    asm volatile("prefetch.global.L2 [%0];" :: "l"(rr + basep + (size_t)m * Dm));
                    asm volatile("prefetch.global.L2 [%0];" :: "l"(noise + basep + (size_t)m * Dm));
                }
            }
            const int g  = d & 63;
            const int rp = d >> 6;
            const char* wbase = (const char*)Wm + g * 16;
            #pragma unroll
            for (int t = 0; t < 2; t++) {
                const int m = rp + t * 4;
                const int cnt  = fcnt[m];
                const int full = cnt & ~3;
                const int* fl = flist[m];
                const int4* fl4 = reinterpret_cast<const int4*>(fl);
                float4 acc = *reinterpret_cast<const float4*>(&xh[m * Dm + g * 4]);
                int4 en = fl4[0];
                #pragma unroll 2
                for (int i = 0; i < full; i += 4) {
                    int4 e = en;
                    en = fl4[(i >> 2) + 1];
                    float4 w0 = *reinterpret_cast<const float4*>(wbase + (e.x & OFMASK));
                    float4 w1 = *reinterpret_cast<const float4*>(wbase + (e.y & OFMASK));
                    float4 w2 = *reinterpret_cast<const float4*>(wbase + (e.z & OFMASK));
                    float4 w3 = *reinterpret_cast<const float4*>(wbase + (e.w & OFMASK));
                    acc.x += sxor(w0.x, e.x); acc.y += sxor(w0.y, e.x);
                    acc.z += sxor(w0.z, e.x); acc.w += sxor(w0.w, e.x);
                    acc.x += sxor(w1.x, e.y); acc.y += sxor(w1.y, e.y);
                    acc.z += sxor(w1.z, e.y); acc.w += sxor(w1.w, e.y);
                    acc.x += sxor(w2.x, e.z); acc.y += sxor(w2.y, e.z);
                    acc.z += sxor(w2.z, e.z); acc.w += sxor(w2.w, e.z);
                    acc.x += sxor(w3.x, e.w); acc.y += sxor(w3.y, e.w);
                    acc.z += sxor(w3.z, e.w); acc.w += sxor(w3.w, e.w);
                }
                if (cnt & 3) {   // one padded tail group: fmaf(sv in {+1,-1,0}) exact
                    #pragma unroll
                    for (int j = 0; j < 4; j++) {
                        int e = fl[full + j];
                        float sv = (e & PADB) ? 0.0f : ((e < 0) ? -1.0f : 1.0f);
                        float4 w = *reinterpret_cast<const float4*>(wbase + (e & OFMASK));
                        acc.x = fmaf(sv, w.x, acc.x);
                        acc.y = fmaf(sv, w.y, acc.y);
                        acc.z = fmaf(sv, w.z, acc.z);
                        acc.w = fmaf(sv, w.w, acc.w);
                    }
                }
                *reinterpret_cast<float4*>(&h2s[m][g * 4]) = acc;
            }
        }
        __syncthreads();

        // ---- stage 2b: reverse terms + per-row la reduce (owner thread d) ----
        #pragma unroll
        for (int m = 0; m < Mrows; m++) {
            float acc  = h2s[m][d];
            float xdav = xdas[m][d];
            float xf   = ((xmask >> m) & 1u) ? 1.0f : 0.0f;
            bool  ind  = (indmask >> m) & 1u;
            float xdv  = ind ? 1.0f - xf : xf;
            float sgn2 = 1.0f - 2.0f * xdv;
            float ga2  = (xdv - xdav) * 1e-4f;
            float hb2  = acc + bd;
            float gm2  = (hb2 * sgn2) * 0.5f - (ga2 * 0.5f) * sgn2;
            float fp2  = my_sigmoid(gm2 - 2.5f);
            float lpr  = my_log((ind ? fp2 : 1.0f - fp2) + 1e-10f);
            float e2   = (xdv != 0.0f) ? fmaf(0.5f, acc, bd) : 0.0f;
            float dxd  = xdv - xdav;
            float inner2 = fmaf(0.25f, ga2, xdav);
            float q2   = xa[m] - inner2;
            float t = taccs[m][d] + lpr + e2 - fmaf(dxd * dxd, 5e-5f, q2 * q2);

            t += __shfl_down_sync(0xffffffffu, t, 16);
            t += __shfl_down_sync(0xffffffffu, t, 8);
            t += __shfl_down_sync(0xffffffffu, t, 4);
            t += __shfl_down_sync(0xffffffffu, t, 2);
            t += __shfl_down_sync(0xffffffffu, t, 1);
            if (lane == 0) red[m][warp] = t;
        }
        __syncthreads();

        // ---- MH accept per row ----
        if (d < Mrows) {
            float la = 0.0f;
            #pragma unroll
            for (int w2 = 0; w2 < NW; w2++) la += red[d][w2];
            float u = __ldcs(&au[step * Bm + rowBase + d]);
            float lu = (u > 0.0f) ? my_log(u) : -3.0e38f;
            accs[d] = (la > lu) ? 1.0f : 0.0f;
        }
        __syncthreads();

        // ---- commit (thread-private slots only; next barrier is after stage 1) ----
        #pragma unroll
        for (int m = 0; m < Mrows; m++) {
            if (accs[m] != 0.0f) {
                xa[m] = xdas[m][d];
                xh[m * Dm + d] = h2s[m][d];
                xmask ^= (indmask & (1u << m));
            }
        }
    }

    #pragma unroll
    for (int m = 0; m < Mrows; m++) {
        float xf = ((xmask >> m) & 1u) ? 1.0f : 0.0f;
        __stcs(&out[(size_t)(rowBase + m) * Dm + d], xf);
        __stcs(&out[(size_t)Bm * Dm + (size_t)(rowBase + m) * Dm + d], xa[m]);
    }
}

extern "C" void kernel_launch(void* const* d_in, const int* in_sizes, int n_in,
                              void* d_out, int out_size) {
    const float* x  = (const float*)d_in[0];
    const float* xa = (const float*)d_in[1];
    const float* W  = (const float*)d_in[2];
    const float* b  = (const float*)d_in[3];
    const float* rr = (const float*)d_in[4];
    const float* nz = (const float*)d_in[5];
    const float* au = (const float*)d_in[6];
    els_kernel<<<Bm / Mrows, 256>>>(x, xa, W, b, rr, nz, au, (float*)d_out);
}

// round 13
// speedup vs baseline: 1.1363x; 1.0050x over previous
#include <cuda_runtime.h>
#include <stdint.h>

#define Dm 256
#define Bm 16384
#define NSTEPS 5
#define Mrows 8
#define NW 8
#define LCAP 264

#define SIGNB 0x80000000
#define PADB  0x40000000
#define OFMASK 0x0003FC00   // idx<<10 (byte offset of W row) for idx<256

// ---- flag-independent fp32 exp/log/sigmoid (pure FMA; sigmoid keeps __fdiv_rn) ----

static __device__ __forceinline__ float my_exp(float x) {
    x = fmaxf(x, -80.0f);
    float z = x * 1.4426950408889634f;
    float n = rintf(z);
    float r = fmaf(n, -0.693359375f, x);
    r = fmaf(n, 2.12194440054690583e-4f, r);
    float p = 1.9841269841269841e-4f;
    p = fmaf(p, r, 1.3888888888888889e-3f);
    p = fmaf(p, r, 8.3333333333333333e-3f);
    p = fmaf(p, r, 4.1666666666666664e-2f);
    p = fmaf(p, r, 1.6666666666666666e-1f);
    p = fmaf(p, r, 0.5f);
    p = fmaf(p, r, 1.0f);
    p = fmaf(p, r, 1.0f);
    int ni = (int)n;
    return p * __int_as_float((127 + ni) << 23);
}

static __device__ __forceinline__ float my_log(float v) {
    int i = __float_as_int(v);
    int e = (i - 0x3f3504f3) >> 23;
    float m = __int_as_float(i - (e << 23));
    float f = m - 1.0f;
    float z = f * f;
    float p = 7.0376836292e-2f;
    p = fmaf(p, f, -1.1514610310e-1f);
    p = fmaf(p, f, 1.1676998740e-1f);
    p = fmaf(p, f, -1.2420140846e-1f);
    p = fmaf(p, f, 1.4249322787e-1f);
    p = fmaf(p, f, -1.6668057665e-1f);
    p = fmaf(p, f, 2.0000714765e-1f);
    p = fmaf(p, f, -2.4999993993e-1f);
    p = fmaf(p, f, 3.3333331174e-1f);
    float r = fmaf(p * z, f, fmaf(-0.5f, z, f));
    float ef = (float)e;
    return fmaf(ef, 0.693359375f, fmaf(ef, -2.12194440054690583e-4f, r));
}

static __device__ __forceinline__ float my_sigmoid(float t) {   // decision-critical: unchanged
    float en = my_exp(-fabsf(t));
    float s = __fdiv_rn(en, 1.0f + en);
    return (t > 0.0f) ? 1.0f - s : s;
}

static __device__ __forceinline__ float sxor(float w, int e) {  // w * sign(e) via bit xor
    return __int_as_float(__float_as_int(w) ^ (e & SIGNB));
}

// ---- fused sampler: one block = 8 chains; thread d owns dim d for math,
// ---- gathers re-map to (64 dim-quads x 4 row-pairs) with LDG.128 ----

__global__ void __launch_bounds__(256, 4)
els_kernel(const float* __restrict__ x_in, const float* __restrict__ xa_in,
           const float* __restrict__ Wm, const float* __restrict__ bv,
           const float* __restrict__ rr, const float* __restrict__ noise,
           const float* __restrict__ au, float* __restrict__ out)
{
    const int d = threadIdx.x;
    const int warp = d >> 5;
    const int lane = d & 31;
    const int rowBase = blockIdx.x * Mrows;

    __shared__ float   xh[Mrows * Dm];         // h state, [m*256 + d]
    __shared__ unsigned posw[Mrows][NW];
    __shared__ unsigned negw[Mrows][NW];
    __shared__ int     flist[Mrows][LCAP];     // packed: sign | (idx<<10); PADB = pad
    __shared__ int     fcnt[Mrows];            // exact count
    __shared__ float   red[Mrows][NW];
    __shared__ float   accs[Mrows];
    __shared__ float   xdas[Mrows][Dm];
    __shared__ float   taccs[Mrows][Dm];
    __shared__ float   h2s[Mrows][Dm];

    const float bd = bv[d];
    float xa[Mrows];
    unsigned xmask = 0;

    // ---- load x/xa; ballot x-bits into posw (init "flip list" = ones of x) ----
    #pragma unroll
    for (int m = 0; m < Mrows; m++) {
        float xv = __ldcs(&x_in[(size_t)(rowBase + m) * Dm + d]);
        xa[m] = __ldcs(&xa_in[(size_t)(rowBase + m) * Dm + d]);
        bool one = xv != 0.0f;
        if (one) xmask |= (1u << m);
        unsigned pb = __ballot_sync(0xffffffffu, one);
        if (lane == 0) { posw[m][warp] = pb; negw[m][warp] = 0u; }
    }
    // prefetch step-0 rr/noise lines + au lines into L2 while init runs
    if (lane == 0) {
        size_t base0 = (size_t)rowBase * Dm + (warp << 5);
        #pragma unroll
        for (int m = 0; m < Mrows; m++) {
            asm volatile("prefetch.global.L2 [%0];" :: "l"(rr + base0 + (size_t)m * Dm));
            asm volatile("prefetch.global.L2 [%0];" :: "l"(noise + base0 + (size_t)m * Dm));
        }
    }
    if (d == 0) {
        #pragma unroll
        for (int s = 0; s < NSTEPS; s++)
            asm volatile("prefetch.global.L2 [%0];" :: "l"(au + (size_t)s * Bm + rowBase));
    }
    __syncthreads();

    // ---- build init lists (64 threads; negw==0 -> pos only + pad) ----
    if (d < Mrows * NW) {
        int m = d >> 3, c = d & 7;
        int off = 0;
        #pragma unroll
        for (int c2 = 0; c2 < NW; c2++) {
            int cnt = __popc(posw[m][c2]);
            if (c2 < c) off += cnt;
        }
        int base = c * 32;
        unsigned pw = posw[m][c];
        while (pw) { int j = __ffs(pw) - 1; pw &= pw - 1; flist[m][off++] = (base + j) << 10; }
        if (c == NW - 1) {
            int padded = (off + 3) & ~3;
            for (int i = off; i < padded; i++) flist[m][i] = PADB;
            fcnt[m] = off;
        }
    }
    __syncthreads();

    // ---- init gather: h = sum_{e: x=1} W[e][:]  (== FMA loop skipping exact
    // ---- zeros, ascending e => bit-identical to the dense matvec) ----
    {
        const int g  = d & 63;
        const int rp = d >> 6;
        const char* wbase = (const char*)Wm + g * 16;
        #pragma unroll
        for (int t = 0; t < 2; t++) {
            const int m = rp + t * 4;
            const int cnt  = fcnt[m];
            const int full = cnt & ~3;
            const int* fl = flist[m];
            const int4* fl4 = reinterpret_cast<const int4*>(fl);
            float4 acc = make_float4(0.0f, 0.0f, 0.0f, 0.0f);
            int4 en = fl4[0];
            for (int i = 0; i < full; i += 4) {
                int4 e = en;
                en = fl4[(i >> 2) + 1];
                float4 w0 = *reinterpret_cast<const float4*>(wbase + (e.x & OFMASK));
                float4 w1 = *reinterpret_cast<const float4*>(wbase + (e.y & OFMASK));
                float4 w2 = *reinterpret_cast<const float4*>(wbase + (e.z & OFMASK));
                float4 w3 = *reinterpret_cast<const float4*>(wbase + (e.w & OFMASK));
                acc.x += w0.x; acc.y += w0.y; acc.z += w0.z; acc.w += w0.w;
                acc.x += w1.x; acc.y += w1.y; acc.z += w1.z; acc.w += w1.w;
                acc.x += w2.x; acc.y += w2.y; acc.z += w2.z; acc.w += w2.w;
                acc.x += w3.x; acc.y += w3.y; acc.z += w3.z; acc.w += w3.w;
            }
            if (cnt & 3) {
                #pragma unroll
                for (int j = 0; j < 4; j++) {
                    int e = fl[full + j];
                    float sv = (e & PADB) ? 0.0f : 1.0f;
                    float4 w = *reinterpret_cast<const float4*>(wbase + (e & OFMASK));
                    acc.x = fmaf(sv, w.x, acc.x);
                    acc.y = fmaf(sv, w.y, acc.y);
                    acc.z = fmaf(sv, w.z, acc.z);
                    acc.w = fmaf(sv, w.w, acc.w);
                }
            }
            *reinterpret_cast<float4*>(&xh[m * Dm + g * 4]) = acc;
        }
    }
    __syncthreads();

    for (int step = 0; step < NSTEPS; step++) {
        unsigned indmask = 0;

        // ---- stage 1: propose flips, forward log-prob terms ----
        #pragma unroll
        for (int m = 0; m < Mrows; m++) {
            float rv  = __ldcs(&rr[((size_t)(step * Bm + rowBase + m)) * Dm + d]);
            float nv  = __ldcs(&noise[((size_t)(step * Bm + rowBase + m)) * Dm + d]);
            float hm  = xh[m * Dm + d];
            float xf  = ((xmask >> m) & 1u) ? 1.0f : 0.0f;
            float sgn = 1.0f - 2.0f * xf;                    // -(2x-1)
            float ga  = (xf - xa[m]) * 1e-4f;                // (x - xa)/ETA
            float hb  = hm + bd;
            float gm  = (hb * sgn) * 0.5f - (ga * 0.5f) * sgn;
            float fp  = my_sigmoid(gm - 2.5f);
            bool ind  = rv < fp;
            float inner = xa[m] + 0.25f * ga;
            float pn  = __fmul_rn(0.70710678118654752f, nv);
            float xdav = inner + pn;
            float lpf = my_log((ind ? fp : 1.0f - fp) + 1e-10f);
            float e1  = (xf != 0.0f) ? fmaf(0.5f, hm, bd) : 0.0f;  // x*(0.5h+b)
            float dxa = xf - xa[m];
            float q1  = xdav - inner;
            taccs[m][d] = fmaf(dxa * dxa, 5e-5f, q1 * q1) - lpf - e1;
            if (ind) indmask |= (1u << m);
            unsigned pb = __ballot_sync(0xffffffffu, ind && xf == 0.0f);
            unsigned nb = __ballot_sync(0xffffffffu, ind && xf != 0.0f);
            if (lane == 0) { posw[m][warp] = pb; negw[m][warp] = nb; }
            xdas[m][d] = xdav;
        }
        __syncthreads();

        // ---- stage 1b: expand bitmasks into per-row packed flip lists ----
        // Order per row: chunk 0..7, pos asc then neg asc (bit-identical h2 order).
        if (d < Mrows * NW) {
            int m = d >> 3, c = d & 7;
            int off = 0;
            #pragma unroll
            for (int c2 = 0; c2 < NW; c2++) {
                int cnt = __popc(posw[m][c2]) + __popc(negw[m][c2]);
                if (c2 < c) off += cnt;
            }
            int base = c * 32;
            unsigned pw = posw[m][c];
            while (pw) { int j = __ffs(pw) - 1; pw &= pw - 1; flist[m][off++] = (base + j) << 10; }
            unsigned nw_ = negw[m][c];
            while (nw_) { int j = __ffs(nw_) - 1; nw_ &= nw_ - 1; flist[m][off++] = (int)(SIGNB | (unsigned)((base + j) << 10)); }
            if (c == NW - 1) {
                int padded = (off + 3) & ~3;
                for (int i = off; i < padded; i++) flist[m][i] = PADB;
                fcnt[m] = off;
            }
        }
        __syncthreads();

        // ---- stage 2a: per-row gathers (+ L2 prefetch of next step's streams) ----
        {
            if (lane == 0 && step + 1 < NSTEPS) {
                size_t basep = ((size_t)((step + 1) * Bm + rowBase)) * Dm + (warp << 5);
                #pragma unroll
                for (int m = 0; m < Mrows; m++) {
                    asm volatile("prefetch.global.L2 [%0];" :: "l"(rr + basep + (size_t)m * Dm));
                    asm volatile("prefetch.global.L2 [%0];" :: "l"(noise + basep + (size_t)m * Dm));
                }
            }
            const int g  = d & 63;
            const int rp = d >> 6;
            const char* wbase = (const char*)Wm + g * 16;
            #pragma unroll
            for (int t = 0; t < 2; t++) {
                const int m = rp + t * 4;
                const int cnt  = fcnt[m];
                const int full = cnt & ~3;
                const int* fl = flist[m];
                const int4* fl4 = reinterpret_cast<const int4*>(fl);
                float4 acc = *reinterpret_cast<const float4*>(&xh[m * Dm + g * 4]);
                int4 en = fl4[0];
                for (int i = 0; i < full; i += 4) {
                    int4 e = en;
                    en = fl4[(i >> 2) + 1];
                    float4 w0 = *reinterpret_cast<const float4*>(wbase + (e.x & OFMASK));
                    float4 w1 = *reinterpret_cast<const float4*>(wbase + (e.y & OFMASK));
                    float4 w2 = *reinterpret_cast<const float4*>(wbase + (e.z & OFMASK));
                    float4 w3 = *reinterpret_cast<const float4*>(wbase + (e.w & OFMASK));
                    acc.x += sxor(w0.x, e.x); acc.y += sxor(w0.y, e.x);
                    acc.z += sxor(w0.z, e.x); acc.w += sxor(w0.w, e.x);
                    acc.x += sxor(w1.x, e.y); acc.y += sxor(w1.y, e.y);
                    acc.z += sxor(w1.z, e.y); acc.w += sxor(w1.w, e.y);
                    acc.x += sxor(w2.x, e.z); acc.y += sxor(w2.y, e.z);
                    acc.z += sxor(w2.z, e.z); acc.w += sxor(w2.w, e.z);
                    acc.x += sxor(w3.x, e.w); acc.y += sxor(w3.y, e.w);
                    acc.z += sxor(w3.z, e.w); acc.w += sxor(w3.w, e.w);
                }
                if (cnt & 3) {   // one padded tail group: fmaf(sv in {+1,-1,0}) exact
                    #pragma unroll
                    for (int j = 0; j < 4; j++) {
                        int e = fl[full + j];
                        float sv = (e & PADB) ? 0.0f : ((e < 0) ? -1.0f : 1.0f);
                        float4 w = *reinterpret_cast<const float4*>(wbase + (e & OFMASK));
                        acc.x = fmaf(sv, w.x, acc.x);
                        acc.y = fmaf(sv, w.y, acc.y);
                        acc.z = fmaf(sv, w.z, acc.z);
                        acc.w = fmaf(sv, w.w, acc.w);
                    }
                }
                *reinterpret_cast<float4*>(&h2s[m][g * 4]) = acc;
            }
        }
        __syncthreads();

        // ---- stage 2b: reverse terms + per-row la reduce (owner thread d) ----
        #pragma unroll
        for (int m = 0; m < Mrows; m++) {
            float acc  = h2s[m][d];
            float xdav = xdas[m][d];
            float xf   = ((xmask >> m) & 1u) ? 1.0f : 0.0f;
            bool  ind  = (indmask >> m) & 1u;
            float xdv  = ind ? 1.0f - xf : xf;
            float sgn2 = 1.0f - 2.0f * xdv;
            float ga2  = (xdv - xdav) * 1e-4f;
            float hb2  = acc + bd;
            float gm2  = (hb2 * sgn2) * 0.5f - (ga2 * 0.5f) * sgn2;
            float fp2  = my_sigmoid(gm2 - 2.5f);
            float lpr  = my_log((ind ? fp2 : 1.0f - fp2) + 1e-10f);
            float e2   = (xdv != 0.0f) ? fmaf(0.5f, acc, bd) : 0.0f;
            float dxd  = xdv - xdav;
            float inner2 = fmaf(0.25f, ga2, xdav);
            float q2   = xa[m] - inner2;
            float t = taccs[m][d] + lpr + e2 - fmaf(dxd * dxd, 5e-5f, q2 * q2);

            t += __shfl_down_sync(0xffffffffu, t, 16);
            t += __shfl_down_sync(0xffffffffu, t, 8);
            t += __shfl_down_sync(0xffffffffu, t, 4);
            t += __shfl_down_sync(0xffffffffu, t, 2);
            t += __shfl_down_sync(0xffffffffu, t, 1);
            if (lane == 0) red[m][warp] = t;
        }
        __syncthreads();

        // ---- MH accept per row ----
        if (d < Mrows) {
            float la = 0.0f;
            #pragma unroll
            for (int w2 = 0; w2 < NW; w2++) la += red[d][w2];
            float u = __ldcs(&au[step * Bm + rowBase + d]);
            float lu = (u > 0.0f) ? my_log(u) : -3.0e38f;
            accs[d] = (la > lu) ? 1.0f : 0.0f;
        }
        __syncthreads();

        // ---- commit (thread-private slots only; next barrier is after stage 1) ----
        #pragma unroll
        for (int m = 0; m < Mrows; m++) {
            if (accs[m] != 0.0f) {
                xa[m] = xdas[m][d];
                xh[m * Dm + d] = h2s[m][d];
                xmask ^= (indmask & (1u << m));
            }
        }
    }

    #pragma unroll
    for (int m = 0; m < Mrows; m++) {
        float xf = ((xmask >> m) & 1u) ? 1.0f : 0.0f;
        __stcs(&out[(size_t)(rowBase + m) * Dm + d], xf);
        __stcs(&out[(size_t)Bm * Dm + (size_t)(rowBase + m) * Dm + d], xa[m]);
    }
}

extern "C" void kernel_launch(void* const* d_in, const int* in_sizes, int n_in,
                              void* d_out, int out_size) {
    const float* x  = (const float*)d_in[0];
    const float* xa = (const float*)d_in[1];
    const float* W  = (const float*)d_in[2];
    const float* b  = (const float*)d_in[3];
    const float* rr = (const float*)d_in[4];
    const float* nz = (const float*)d_in[5];
    const float* au = (const float*)d_in[6];
    els_kernel<<<Bm / Mrows, 256>>>(x, xa, W, b, rr, nz, au, (float*)d_out);
}

// round 14
// speedup vs baseline: 1.1382x; 1.0016x over previous
#include <cuda_runtime.h>
#include <stdint.h>

#define Dm 256
#define Bm 16384
#define NSTEPS 5
#define Mrows 8
#define NW 8
#define LCAP 264

#define SIGNB 0x80000000
#define PADB  0x40000000
#define OFMASK 0x0003FC00   // idx<<10 (byte offset of W row) for idx<256

// ---- flag-independent fp32 exp/log/sigmoid (pure FMA; sigmoid keeps __fdiv_rn) ----

static __device__ __forceinline__ float my_exp(float x) {
    x = fmaxf(x, -80.0f);
    float z = x * 1.4426950408889634f;
    float n = rintf(z);
    float r = fmaf(n, -0.693359375f, x);
    r = fmaf(n, 2.12194440054690583e-4f, r);
    float p = 1.9841269841269841e-4f;
    p = fmaf(p, r, 1.3888888888888889e-3f);
    p = fmaf(p, r, 8.3333333333333333e-3f);
    p = fmaf(p, r, 4.1666666666666664e-2f);
    p = fmaf(p, r, 1.6666666666666666e-1f);
    p = fmaf(p, r, 0.5f);
    p = fmaf(p, r, 1.0f);
    p = fmaf(p, r, 1.0f);
    int ni = (int)n;
    return p * __int_as_float((127 + ni) << 23);
}

static __device__ __forceinline__ float my_log(float v) {
    int i = __float_as_int(v);
    int e = (i - 0x3f3504f3) >> 23;
    float m = __int_as_float(i - (e << 23));
    float f = m - 1.0f;
    float z = f * f;
    float p = 7.0376836292e-2f;
    p = fmaf(p, f, -1.1514610310e-1f);
    p = fmaf(p, f, 1.1676998740e-1f);
    p = fmaf(p, f, -1.2420140846e-1f);
    p = fmaf(p, f, 1.4249322787e-1f);
    p = fmaf(p, f, -1.6668057665e-1f);
    p = fmaf(p, f, 2.0000714765e-1f);
    p = fmaf(p, f, -2.4999993993e-1f);
    p = fmaf(p, f, 3.3333331174e-1f);
    float r = fmaf(p * z, f, fmaf(-0.5f, z, f));
    float ef = (float)e;
    return fmaf(ef, 0.693359375f, fmaf(ef, -2.12194440054690583e-4f, r));
}

static __device__ __forceinline__ float my_sigmoid(float t) {   // decision-critical: unchanged
    float en = my_exp(-fabsf(t));
    float s = __fdiv_rn(en, 1.0f + en);
    return (t > 0.0f) ? 1.0f - s : s;
}

static __device__ __forceinline__ float sxor(float w, int e) {  // w * sign(e) via bit xor
    return __int_as_float(__float_as_int(w) ^ (e & SIGNB));
}

// ---- fused sampler: one block = 8 chains; thread d owns dim d for math,
// ---- gathers re-map to (64 dim-quads x 4 row-pairs) with LDG.128 ----

__global__ void __launch_bounds__(256, 4)
els_kernel(const float* __restrict__ x_in, const float* __restrict__ xa_in,
           const float* __restrict__ Wm, const float* __restrict__ bv,
           const float* __restrict__ rr, const float* __restrict__ noise,
           const float* __restrict__ au, float* __restrict__ out)
{
    const int d = threadIdx.x;
    const int warp = d >> 5;
    const int lane = d & 31;
    const int rowBase = blockIdx.x * Mrows;

    __shared__ float   xh[Mrows * Dm];         // h state, [m*256 + d]
    __shared__ unsigned posw[Mrows][NW];
    __shared__ unsigned negw[Mrows][NW];
    __shared__ int     flist[Mrows][LCAP];     // packed: sign | (idx<<10); PADB = pad
    __shared__ int     fcnt[Mrows];            // exact count
    __shared__ float   red[Mrows][NW];
    __shared__ float   xdas[Mrows][Dm];
    __shared__ float   taccs[Mrows][Dm];
    __shared__ float   h2s[Mrows][Dm];

    const float bd = bv[d];
    float xa[Mrows];
    unsigned xmask = 0;

    // ---- load x/xa; ballot x-bits into posw (init "flip list" = ones of x) ----
    #pragma unroll
    for (int m = 0; m < Mrows; m++) {
        float xv = __ldcs(&x_in[(size_t)(rowBase + m) * Dm + d]);
        xa[m] = __ldcs(&xa_in[(size_t)(rowBase + m) * Dm + d]);
        bool one = xv != 0.0f;
        if (one) xmask |= (1u << m);
        unsigned pb = __ballot_sync(0xffffffffu, one);
        if (lane == 0) { posw[m][warp] = pb; negw[m][warp] = 0u; }
    }
    // prefetch step-0 rr/noise lines + au lines into L2 while init runs
    if (lane == 0) {
        size_t base0 = (size_t)rowBase * Dm + (warp << 5);
        #pragma unroll
        for (int m = 0; m < Mrows; m++) {
            asm volatile("prefetch.global.L2 [%0];" :: "l"(rr + base0 + (size_t)m * Dm));
            asm volatile("prefetch.global.L2 [%0];" :: "l"(noise + base0 + (size_t)m * Dm));
        }
    }
    if (d == 0) {
        #pragma unroll
        for (int s = 0; s < NSTEPS; s++)
            asm volatile("prefetch.global.L2 [%0];" :: "l"(au + (size_t)s * Bm + rowBase));
    }
    __syncthreads();

    // ---- build init lists (64 threads; negw==0 -> pos only + pad) ----
    if (d < Mrows * NW) {
        int m = d >> 3, c = d & 7;
        int off = 0;
        #pragma unroll
        for (int c2 = 0; c2 < NW; c2++) {
            int cnt = __popc(posw[m][c2]);
            if (c2 < c) off += cnt;
        }
        int base = c * 32;
        unsigned pw = posw[m][c];
        while (pw) { int j = __ffs(pw) - 1; pw &= pw - 1; flist[m][off++] = (base + j) << 10; }
        if (c == NW - 1) {
            int padded = (off + 3) & ~3;
            for (int i = off; i < padded; i++) flist[m][i] = PADB;
            fcnt[m] = off;
        }
    }
    __syncthreads();

    // ---- init gather: h = sum_{e: x=1} W[e][:]  (== FMA loop skipping exact
    // ---- zeros, ascending e => bit-identical to the dense matvec) ----
    {
        const int g  = d & 63;
        const int rp = d >> 6;
        const char* wbase = (const char*)Wm + g * 16;
        #pragma unroll
        for (int t = 0; t < 2; t++) {
            const int m = rp + t * 4;
            const int cnt  = fcnt[m];
            const int full = cnt & ~3;
            const int* fl = flist[m];
            const int4* fl4 = reinterpret_cast<const int4*>(fl);
            float4 acc = make_float4(0.0f, 0.0f, 0.0f, 0.0f);
            int4 en = fl4[0];
            for (int i = 0; i < full; i += 4) {
                int4 e = en;
                en = fl4[(i >> 2) + 1];
                float4 w0 = *reinterpret_cast<const float4*>(wbase + (e.x & OFMASK));
                float4 w1 = *reinterpret_cast<const float4*>(wbase + (e.y & OFMASK));
                float4 w2 = *reinterpret_cast<const float4*>(wbase + (e.z & OFMASK));
                float4 w3 = *reinterpret_cast<const float4*>(wbase + (e.w & OFMASK));
                acc.x += w0.x; acc.y += w0.y; acc.z += w0.z; acc.w += w0.w;
                acc.x += w1.x; acc.y += w1.y; acc.z += w1.z; acc.w += w1.w;
                acc.x += w2.x; acc.y += w2.y; acc.z += w2.z; acc.w += w2.w;
                acc.x += w3.x; acc.y += w3.y; acc.z += w3.z; acc.w += w3.w;
            }
            if (cnt & 3) {
                #pragma unroll
                for (int j = 0; j < 4; j++) {
                    int e = fl[full + j];
                    float sv = (e & PADB) ? 0.0f : 1.0f;
                    float4 w = *reinterpret_cast<const float4*>(wbase + (e & OFMASK));
                    acc.x = fmaf(sv, w.x, acc.x);
                    acc.y = fmaf(sv, w.y, acc.y);
                    acc.z = fmaf(sv, w.z, acc.z);
                    acc.w = fmaf(sv, w.w, acc.w);
                }
            }
            *reinterpret_cast<float4*>(&xh[m * Dm + g * 4]) = acc;
        }
    }
    __syncthreads();

    for (int step = 0; step < NSTEPS; step++) {
        unsigned indmask = 0;

        // ---- stage 1: propose flips, forward log-prob terms ----
        #pragma unroll
        for (int m = 0; m < Mrows; m++) {
            float rv  = __ldcs(&rr[((size_t)(step * Bm + rowBase + m)) * Dm + d]);
            float nv  = __ldcs(&noise[((size_t)(step * Bm + rowBase + m)) * Dm + d]);
            float hm  = xh[m * Dm + d];
            float xf  = ((xmask >> m) & 1u) ? 1.0f : 0.0f;
            float sgn = 1.0f - 2.0f * xf;                    // -(2x-1)
            float ga  = (xf - xa[m]) * 1e-4f;                // (x - xa)/ETA
            float hb  = hm + bd;
            float gm  = (hb * sgn) * 0.5f - (ga * 0.5f) * sgn;
            float fp  = my_sigmoid(gm - 2.5f);
            bool ind  = rv < fp;
            float inner = xa[m] + 0.25f * ga;
            float pn  = __fmul_rn(0.70710678118654752f, nv);
            float xdav = inner + pn;
            float lpf = my_log((ind ? fp : 1.0f - fp) + 1e-10f);
            float e1  = (xf != 0.0f) ? fmaf(0.5f, hm, bd) : 0.0f;  // x*(0.5h+b)
            float dxa = xf - xa[m];
            float q1  = xdav - inner;
            taccs[m][d] = fmaf(dxa * dxa, 5e-5f, q1 * q1) - lpf - e1;
            if (ind) indmask |= (1u << m);
            unsigned pb = __ballot_sync(0xffffffffu, ind && xf == 0.0f);
            unsigned nb = __ballot_sync(0xffffffffu, ind && xf != 0.0f);
            if (lane == 0) { posw[m][warp] = pb; negw[m][warp] = nb; }
            xdas[m][d] = xdav;
        }
        __syncthreads();

        // ---- stage 1b: expand bitmasks into per-row packed flip lists ----
        // Order per row: chunk 0..7, pos asc then neg asc (bit-identical h2 order).
        if (d < Mrows * NW) {
            int m = d >> 3, c = d & 7;
            int off = 0;
            #pragma unroll
            for (int c2 = 0; c2 < NW; c2++) {
                int cnt = __popc(posw[m][c2]) + __popc(negw[m][c2]);
                if (c2 < c) off += cnt;
            }
            int base = c * 32;
            unsigned pw = posw[m][c];
            while (pw) { int j = __ffs(pw) - 1; pw &= pw - 1; flist[m][off++] = (base + j) << 10; }
            unsigned nw_ = negw[m][c];
            while (nw_) { int j = __ffs(nw_) - 1; nw_ &= nw_ - 1; flist[m][off++] = (int)(SIGNB | (unsigned)((base + j) << 10)); }
            if (c == NW - 1) {
                int padded = (off + 3) & ~3;
                for (int i = off; i < padded; i++) flist[m][i] = PADB;
                fcnt[m] = off;
            }
        }
        __syncthreads();

        // ---- stage 2a: per-row gathers (+ L2 prefetch of next step's streams) ----
        {
            if (lane == 0 && step + 1 < NSTEPS) {
                size_t basep = ((size_t)((step + 1) * Bm + rowBase)) * Dm + (warp << 5);
                #pragma unroll
                for (int m = 0; m < Mrows; m++) {
                    asm volatile("prefetch.global.L2 [%0];" :: "l"(rr + basep + (size_t)m * Dm));
                    asm volatile("prefetch.global.L2 [%0];" :: "l"(noise + basep + (size_t)m * Dm));
                }
            }
            const int g  = d & 63;
            const int rp = d >> 6;
            const char* wbase = (const char*)Wm + g * 16;
            #pragma unroll
            for (int t = 0; t < 2; t++) {
                const int m = rp + t * 4;
                const int cnt  = fcnt[m];
                const int full = cnt & ~3;
                const int* fl = flist[m];
                const int4* fl4 = reinterpret_cast<const int4*>(fl);
                float4 acc = *reinterpret_cast<const float4*>(&xh[m * Dm + g * 4]);
                int4 en = fl4[0];
                for (int i = 0; i < full; i += 4) {
                    int4 e = en;
                    en = fl4[(i >> 2) + 1];
                    float4 w0 = *reinterpret_cast<const float4*>(wbase + (e.x & OFMASK));
                    float4 w1 = *reinterpret_cast<const float4*>(wbase + (e.y & OFMASK));
                    float4 w2 = *reinterpret_cast<const float4*>(wbase + (e.z & OFMASK));
                    float4 w3 = *reinterpret_cast<const float4*>(wbase + (e.w & OFMASK));
                    acc.x += sxor(w0.x, e.x); acc.y += sxor(w0.y, e.x);
                    acc.z += sxor(w0.z, e.x); acc.w += sxor(w0.w, e.x);
                    acc.x += sxor(w1.x, e.y); acc.y += sxor(w1.y, e.y);
                    acc.z += sxor(w1.z, e.y); acc.w += sxor(w1.w, e.y);
                    acc.x += sxor(w2.x, e.z); acc.y += sxor(w2.y, e.z);
                    acc.z += sxor(w2.z, e.z); acc.w += sxor(w2.w, e.z);
                    acc.x += sxor(w3.x, e.w); acc.y += sxor(w3.y, e.w);
                    acc.z += sxor(w3.z, e.w); acc.w += sxor(w3.w, e.w);
                }
                if (cnt & 3) {   // one padded tail group: fmaf(sv in {+1,-1,0}) exact
                    #pragma unroll
                    for (int j = 0; j < 4; j++) {
                        int e = fl[full + j];
                        float sv = (e & PADB) ? 0.0f : ((e < 0) ? -1.0f : 1.0f);
                        float4 w = *reinterpret_cast<const float4*>(wbase + (e & OFMASK));
                        acc.x = fmaf(sv, w.x, acc.x);
                        acc.y = fmaf(sv, w.y, acc.y);
                        acc.z = fmaf(sv, w.z, acc.z);
                        acc.w = fmaf(sv, w.w, acc.w);
                    }
                }
                *reinterpret_cast<float4*>(&h2s[m][g * 4]) = acc;
            }
        }
        __syncthreads();

        // ---- stage 2b: reverse terms + per-row la reduce (owner thread d) ----
        #pragma unroll
        for (int m = 0; m < Mrows; m++) {
            float acc  = h2s[m][d];
            float xdav = xdas[m][d];
            float xf   = ((xmask >> m) & 1u) ? 1.0f : 0.0f;
            bool  ind  = (indmask >> m) & 1u;
            float xdv  = ind ? 1.0f - xf : xf;
            float sgn2 = 1.0f - 2.0f * xdv;
            float ga2  = (xdv - xdav) * 1e-4f;
            float hb2  = acc + bd;
            float gm2  = (hb2 * sgn2) * 0.5f - (ga2 * 0.5f) * sgn2;
            float fp2  = my_sigmoid(gm2 - 2.5f);
            float lpr  = my_log((ind ? fp2 : 1.0f - fp2) + 1e-10f);
            float e2   = (xdv != 0.0f) ? fmaf(0.5f, acc, bd) : 0.0f;
            float dxd  = xdv - xdav;
            float inner2 = fmaf(0.25f, ga2, xdav);
            float q2   = xa[m] - inner2;
            float t = taccs[m][d] + lpr + e2 - fmaf(dxd * dxd, 5e-5f, q2 * q2);

            t += __shfl_down_sync(0xffffffffu, t, 16);
            t += __shfl_down_sync(0xffffffffu, t, 8);
            t += __shfl_down_sync(0xffffffffu, t, 4);
            t += __shfl_down_sync(0xffffffffu, t, 2);
            t += __shfl_down_sync(0xffffffffu, t, 1);
            if (lane == 0) red[m][warp] = t;
        }
        __syncthreads();

        // ---- MH accept: every warp redundantly computes all 8 flags ----
        // lanes 0..7: row = lane; identical inputs + identical ascending sum
        // order as the old 8-thread stage => bit-identical accept decisions.
        float accv = 0.0f;
        if (lane < Mrows) {
            float la = 0.0f;
            #pragma unroll
            for (int w2 = 0; w2 < NW; w2++) la += red[lane][w2];
            float u = __ldcs(&au[step * Bm + rowBase + lane]);
            float lu = (u > 0.0f) ? my_log(u) : -3.0e38f;
            accv = (la > lu) ? 1.0f : 0.0f;
        }
        // ---- commit immediately (no second barrier): broadcast via shfl ----
        #pragma unroll
        for (int m = 0; m < Mrows; m++) {
            float am = __shfl_sync(0xffffffffu, accv, m);
            if (am != 0.0f) {
                xa[m] = xdas[m][d];
                xh[m * Dm + d] = h2s[m][d];
                xmask ^= (indmask & (1u << m));
            }
        }
        // no __syncthreads: commit wrote only this thread's own xh slot; red[][]
        // is re-written next step only after the stage-1-end barrier.
    }

    #pragma unroll
    for (int m = 0; m < Mrows; m++) {
        float xf = ((xmask >> m) & 1u) ? 1.0f : 0.0f;
        __stcs(&out[(size_t)(rowBase + m) * Dm + d], xf);
        __stcs(&out[(size_t)Bm * Dm + (size_t)(rowBase + m) * Dm + d], xa[m]);
    }
}

extern "C" void kernel_launch(void* const* d_in, const int* in_sizes, int n_in,
                              void* d_out, int out_size) {
    const float* x  = (const float*)d_in[0];
    const float* xa = (const float*)d_in[1];
    const float* W  = (const float*)d_in[2];
    const float* b  = (const float*)d_in[3];
    const float* rr = (const float*)d_in[4];
    const float* nz = (const float*)d_in[5];
    const float* au = (const float*)d_in[6];
    els_kernel<<<Bm / Mrows, 256>>>(x, xa, W, b, rr, nz, au, (float*)d_out);
}

// round 15
// speedup vs baseline: 1.1389x; 1.0006x over previous
#include <cuda_runtime.h>
#include <stdint.h>

#define Dm 256
#define Bm 16384
#define NSTEPS 5
#define Mrows 8
#define NW 8
#define LCAP 264

#define SIGNB 0x80000000
#define PADB  0x40000000
#define OFMASK 0x0003FC00   // idx<<10 (byte offset of W row) for idx<256

// ---- flag-independent fp32 exp/log/sigmoid (pure FMA; sigmoid keeps __fdiv_rn) ----

static __device__ __forceinline__ float my_exp(float x) {
    x = fmaxf(x, -80.0f);
    float z = x * 1.4426950408889634f;
    float n = rintf(z);
    float r = fmaf(n, -0.693359375f, x);
    r = fmaf(n, 2.12194440054690583e-4f, r);
    float p = 1.9841269841269841e-4f;
    p = fmaf(p, r, 1.3888888888888889e-3f);
    p = fmaf(p, r, 8.3333333333333333e-3f);
    p = fmaf(p, r, 4.1666666666666664e-2f);
    p = fmaf(p, r, 1.6666666666666666e-1f);
    p = fmaf(p, r, 0.5f);
    p = fmaf(p, r, 1.0f);
    p = fmaf(p, r, 1.0f);
    int ni = (int)n;
    return p * __int_as_float((127 + ni) << 23);
}

static __device__ __forceinline__ float my_log(float v) {
    int i = __float_as_int(v);
    int e = (i - 0x3f3504f3) >> 23;
    float m = __int_as_float(i - (e << 23));
    float f = m - 1.0f;
    float z = f * f;
    float p = 7.0376836292e-2f;
    p = fmaf(p, f, -1.1514610310e-1f);
    p = fmaf(p, f, 1.1676998740e-1f);
    p = fmaf(p, f, -1.2420140846e-1f);
    p = fmaf(p, f, 1.4249322787e-1f);
    p = fmaf(p, f, -1.6668057665e-1f);
    p = fmaf(p, f, 2.0000714765e-1f);
    p = fmaf(p, f, -2.4999993993e-1f);
    p = fmaf(p, f, 3.3333331174e-1f);
    float r = fmaf(p * z, f, fmaf(-0.5f, z, f));
    float ef = (float)e;
    return fmaf(ef, 0.693359375f, fmaf(ef, -2.12194440054690583e-4f, r));
}

static __device__ __forceinline__ float my_sigmoid(float t) {   // decision-critical: unchanged
    float en = my_exp(-fabsf(t));
    float s = __fdiv_rn(en, 1.0f + en);
    return (t > 0.0f) ? 1.0f - s : s;
}

static __device__ __forceinline__ float sxor(float w, int e) {  // w * sign(e) via bit xor
    return __int_as_float(__float_as_int(w) ^ (e & SIGNB));
}

// ---- fused sampler: one block = 8 chains; thread d owns dim d for math,
// ---- gathers re-map to (64 dim-quads x 4 row-pairs) with LDG.128 ----

__global__ void __launch_bounds__(256, 4)
els_kernel(const float* __restrict__ x_in, const float* __restrict__ xa_in,
           const float* __restrict__ Wm, const float* __restrict__ bv,
           const float* __restrict__ rr, const float* __restrict__ noise,
           const float* __restrict__ au, float* __restrict__ out)
{
    const int d = threadIdx.x;
    const int warp = d >> 5;
    const int lane = d & 31;
    const int rowBase = blockIdx.x * Mrows;

    __shared__ float   xh[Mrows * Dm];         // h state, [m*256 + d]
    __shared__ unsigned posw[Mrows][NW];
    __shared__ unsigned negw[Mrows][NW];
    __shared__ int     flist[Mrows][LCAP];     // packed: sign | (idx<<10); PADB = pad
    __shared__ int     fcnt[Mrows];            // exact count
    __shared__ float   red[Mrows][NW];
    __shared__ float   xdas[Mrows][Dm];
    __shared__ float   taccs[Mrows][Dm];
    __shared__ float   h2s[Mrows][Dm];

    const float bd = bv[d];
    float xa[Mrows];
    unsigned xmask = 0;

    // ---- load x/xa; ballot x-bits into posw (init "flip list" = ones of x) ----
    #pragma unroll
    for (int m = 0; m < Mrows; m++) {
        float xv = __ldcs(&x_in[(size_t)(rowBase + m) * Dm + d]);
        xa[m] = __ldcs(&xa_in[(size_t)(rowBase + m) * Dm + d]);
        bool one = xv != 0.0f;
        if (one) xmask |= (1u << m);
        unsigned pb = __ballot_sync(0xffffffffu, one);
        if (lane == 0) { posw[m][warp] = pb; negw[m][warp] = 0u; }
    }
    // prefetch step-0 rr/noise lines + au lines into L2 while init runs
    if (lane == 0) {
        size_t base0 = (size_t)rowBase * Dm + (warp << 5);
        #pragma unroll
        for (int m = 0; m < Mrows; m++) {
            asm volatile("prefetch.global.L2 [%0];" :: "l"(rr + base0 + (size_t)m * Dm));
            asm volatile("prefetch.global.L2 [%0];" :: "l"(noise + base0 + (size_t)m * Dm));
        }
    }
    if (d == 0) {
        #pragma unroll
        for (int s = 0; s < NSTEPS; s++)
            asm volatile("prefetch.global.L2 [%0];" :: "l"(au + (size_t)s * Bm + rowBase));
    }
    __syncthreads();

    // ---- build init lists (64 threads; negw==0 -> pos only + pad) ----
    if (d < Mrows * NW) {
        int m = d >> 3, c = d & 7;
        int off = 0;
        #pragma unroll
        for (int c2 = 0; c2 < NW; c2++) {
            int cnt = __popc(posw[m][c2]);
            if (c2 < c) off += cnt;
        }
        int base = c * 32;
        unsigned pw = posw[m][c];
        while (pw) { int j = __ffs(pw) - 1; pw &= pw - 1; flist[m][off++] = (base + j) << 10; }
        if (c == NW - 1) {
            int padded = (off + 3) & ~3;
            for (int i = off; i < padded; i++) flist[m][i] = PADB;
            fcnt[m] = off;
        }
    }
    __syncthreads();

    // ---- init gather: h = sum_{e: x=1} W[e][:]  (== FMA loop skipping exact
    // ---- zeros, ascending e => bit-identical to the dense matvec) ----
    {
        const int g  = d & 63;
        const int rp = d >> 6;
        const char* wbase = (const char*)Wm + g * 16;
        #pragma unroll
        for (int t = 0; t < 2; t++) {
            const int m = rp + t * 4;
            const int cnt  = fcnt[m];
            const int full = cnt & ~3;
            const int* fl = flist[m];
            const int4* fl4 = reinterpret_cast<const int4*>(fl);
            float4 acc = make_float4(0.0f, 0.0f, 0.0f, 0.0f);
            int4 en = fl4[0];
            for (int i = 0; i < full; i += 4) {
                int4 e = en;
                en = fl4[(i >> 2) + 1];
                float4 w0 = *reinterpret_cast<const float4*>(wbase + (e.x & OFMASK));
                float4 w1 = *reinterpret_cast<const float4*>(wbase + (e.y & OFMASK));
                float4 w2 = *reinterpret_cast<const float4*>(wbase + (e.z & OFMASK));
                float4 w3 = *reinterpret_cast<const float4*>(wbase + (e.w & OFMASK));
                acc.x += w0.x; acc.y += w0.y; acc.z += w0.z; acc.w += w0.w;
                acc.x += w1.x; acc.y += w1.y; acc.z += w1.z; acc.w += w1.w;
                acc.x += w2.x; acc.y += w2.y; acc.z += w2.z; acc.w += w2.w;
                acc.x += w3.x; acc.y += w3.y; acc.z += w3.z; acc.w += w3.w;
            }
            if (cnt & 3) {
                #pragma unroll
                for (int j = 0; j < 4; j++) {
                    int e = fl[full + j];
                    float sv = (e & PADB) ? 0.0f : 1.0f;
                    float4 w = *reinterpret_cast<const float4*>(wbase + (e & OFMASK));
                    acc.x = fmaf(sv, w.x, acc.x);
                    acc.y = fmaf(sv, w.y, acc.y);
                    acc.z = fmaf(sv, w.z, acc.z);
                    acc.w = fmaf(sv, w.w, acc.w);
                }
            }
            *reinterpret_cast<float4*>(&xh[m * Dm + g * 4]) = acc;
        }
    }
    __syncthreads();

    for (int step = 0; step < NSTEPS; step++) {
        unsigned indmask = 0;

        // ---- stage 1: propose flips, forward log-prob terms ----
        #pragma unroll
        for (int m = 0; m < Mrows; m++) {
            float rv  = __ldcs(&rr[((size_t)(step * Bm + rowBase + m)) * Dm + d]);
            float nv  = __ldcs(&noise[((size_t)(step * Bm + rowBase + m)) * Dm + d]);
            float hm  = xh[m * Dm + d];
            float xf  = ((xmask >> m) & 1u) ? 1.0f : 0.0f;
            float sgn = 1.0f - 2.0f * xf;                    // -(2x-1)
            float ga  = (xf - xa[m]) * 1e-4f;                // (x - xa)/ETA
            float hb  = hm + bd;
            float gm  = (hb * sgn) * 0.5f - (ga * 0.5f) * sgn;
            float fp  = my_sigmoid(gm - 2.5f);
            bool ind  = rv < fp;
            float inner = xa[m] + 0.25f * ga;
            float pn  = __fmul_rn(0.70710678118654752f, nv);
            float xdav = inner + pn;
            float lpf = my_log((ind ? fp : 1.0f - fp) + 1e-10f);
            float e1  = (xf != 0.0f) ? fmaf(0.5f, hm, bd) : 0.0f;  // x*(0.5h+b)
            float dxa = xf - xa[m];
            float q1  = xdav - inner;
            taccs[m][d] = fmaf(dxa * dxa, 5e-5f, q1 * q1) - lpf - e1;
            if (ind) indmask |= (1u << m);
            unsigned pb = __ballot_sync(0xffffffffu, ind && xf == 0.0f);
            unsigned nb = __ballot_sync(0xffffffffu, ind && xf != 0.0f);
            if (lane == 0) { posw[m][warp] = pb; negw[m][warp] = nb; }
            xdas[m][d] = xdav;
        }
        __syncthreads();

        // ---- stage 1b: expand bitmasks into per-row packed flip lists ----
        // Order per row: chunk 0..7, pos asc then neg asc (bit-identical h2 order).
        if (d < Mrows * NW) {
            int m = d >> 3, c = d & 7;
            int off = 0;
            #pragma unroll
            for (int c2 = 0; c2 < NW; c2++) {
                int cnt = __popc(posw[m][c2]) + __popc(negw[m][c2]);
                if (c2 < c) off += cnt;
            }
            int base = c * 32;
            unsigned pw = posw[m][c];
            while (pw) { int j = __ffs(pw) - 1; pw &= pw - 1; flist[m][off++] = (base + j) << 10; }
            unsigned nw_ = negw[m][c];
            while (nw_) { int j = __ffs(nw_) - 1; nw_ &= nw_ - 1; flist[m][off++] = (int)(SIGNB | (unsigned)((base + j) << 10)); }
            if (c == NW - 1) {
                int padded = (off + 3) & ~3;
                for (int i = off; i < padded; i++) flist[m][i] = PADB;
                fcnt[m] = off;
            }
        }
        __syncthreads();

        // ---- stage 2a: per-row gathers (+ L2 prefetch of next step's streams) ----
        {
            if (lane == 0 && step + 1 < NSTEPS) {
                size_t basep = ((size_t)((step + 1) * Bm + rowBase)) * Dm + (warp << 5);
                #pragma unroll
                for (int m = 0; m < Mrows; m++) {
                    asm volatile("prefetch.global.L2 [%0];" :: "l"(rr + basep + (size_t)m * Dm));
                    asm volatile("prefetch.global.L2 [%0];" :: "l"(noise + basep + (size_t)m * Dm));
                }
            }
            const int g  = d & 63;
            const int rp = d >> 6;
            const char* wbase = (const char*)Wm + g * 16;
            #pragma unroll
            for (int t = 0; t < 2; t++) {
                const int m = rp + t * 4;
                const int cnt  = fcnt[m];
                const int full = cnt & ~3;
                const int* fl = flist[m];
                const int4* fl4 = reinterpret_cast<const int4*>(fl);
                float4 acc = *reinterpret_cast<const float4*>(&xh[m * Dm + g * 4]);
                int4 en = fl4[0];
                for (int i = 0; i < full; i += 4) {
                    int4 e = en;
                    en = fl4[(i >> 2) + 1];
                    float4 w0 = *reinterpret_cast<const float4*>(wbase + (e.x & OFMASK));
                    float4 w1 = *reinterpret_cast<const float4*>(wbase + (e.y & OFMASK));
                    float4 w2 = *reinterpret_cast<const float4*>(wbase + (e.z & OFMASK));
                    float4 w3 = *reinterpret_cast<const float4*>(wbase + (e.w & OFMASK));
                    acc.x += sxor(w0.x, e.x); acc.y += sxor(w0.y, e.x);
                    acc.z += sxor(w0.z, e.x); acc.w += sxor(w0.w, e.x);
                    acc.x += sxor(w1.x, e.y); acc.y += sxor(w1.y, e.y);
                    acc.z += sxor(w1.z, e.y); acc.w += sxor(w1.w, e.y);
                    acc.x += sxor(w2.x, e.z); acc.y += sxor(w2.y, e.z);
                    acc.z += sxor(w2.z, e.z); acc.w += sxor(w2.w, e.z);
                    acc.x += sxor(w3.x, e.w); acc.y += sxor(w3.y, e.w);
                    acc.z += sxor(w3.z, e.w); acc.w += sxor(w3.w, e.w);
                }
                if (cnt & 3) {   // one padded tail group: fmaf(sv in {+1,-1,0}) exact
                    #pragma unroll
                    for (int j = 0; j < 4; j++) {
                        int e = fl[full + j];
                        float sv = (e & PADB) ? 0.0f : ((e < 0) ? -1.0f : 1.0f);
                        float4 w = *reinterpret_cast<const float4*>(wbase + (e & OFMASK));
                        acc.x = fmaf(sv, w.x, acc.x);
                        acc.y = fmaf(sv, w.y, acc.y);
                        acc.z = fmaf(sv, w.z, acc.z);
                        acc.w = fmaf(sv, w.w, acc.w);
                    }
                }
                *reinterpret_cast<float4*>(&h2s[m][g * 4]) = acc;
            }
        }
        __syncthreads();

        // ---- stage 2b: reverse terms + per-row la reduce (owner thread d) ----
        #pragma unroll
        for (int m = 0; m < Mrows; m++) {
            float acc  = h2s[m][d];
            float xdav = xdas[m][d];
            float xf   = ((xmask >> m) & 1u) ? 1.0f : 0.0f;
            bool  ind  = (indmask >> m) & 1u;
            float xdv  = ind ? 1.0f - xf : xf;
            float sgn2 = 1.0f - 2.0f * xdv;
            float ga2  = (xdv - xdav) * 1e-4f;
            float hb2  = acc + bd;
            float gm2  = (hb2 * sgn2) * 0.5f - (ga2 * 0.5f) * sgn2;
            float fp2  = my_sigmoid(gm2 - 2.5f);
            float lpr  = my_log((ind ? fp2 : 1.0f - fp2) + 1e-10f);
            float e2   = (xdv != 0.0f) ? fmaf(0.5f, acc, bd) : 0.0f;
            float dxd  = xdv - xdav;
            float inner2 = fmaf(0.25f, ga2, xdav);
            float q2   = xa[m] - inner2;
            float t = taccs[m][d] + lpr + e2 - fmaf(dxd * dxd, 5e-5f, q2 * q2);

            t += __shfl_down_sync(0xffffffffu, t, 16);
            t += __shfl_down_sync(0xffffffffu, t, 8);
            t += __shfl_down_sync(0xffffffffu, t, 4);
            t += __shfl_down_sync(0xffffffffu, t, 2);
            t += __shfl_down_sync(0xffffffffu, t, 1);
            if (lane == 0) red[m][warp] = t;
        }
        __syncthreads();

        // ---- MH accept: every warp redundantly computes all 8 flags ----
        // lanes 0..7: row = lane; identical inputs + identical ascending sum
        // order as an 8-thread stage => bit-identical accept decisions.
        float accv = 0.0f;
        if (lane < Mrows) {
            float la = 0.0f;
            #pragma unroll
            for (int w2 = 0; w2 < NW; w2++) la += red[lane][w2];
            float u = __ldcs(&au[step * Bm + rowBase + lane]);
            float lu = (u > 0.0f) ? my_log(u) : -3.0e38f;
            accv = (la > lu) ? 1.0f : 0.0f;
        }
        // ---- commit immediately (no second barrier): broadcast via shfl ----
        #pragma unroll
        for (int m = 0; m < Mrows; m++) {
            float am = __shfl_sync(0xffffffffu, accv, m);
            if (am != 0.0f) {
                xa[m] = xdas[m][d];
                xh[m * Dm + d] = h2s[m][d];
                xmask ^= (indmask & (1u << m));
            }
        }
        // no __syncthreads: commit wrote only this thread's own xh slot; red[][]
        // is re-written next step only after the stage-1-end barrier.
    }

    #pragma unroll
    for (int m = 0; m < Mrows; m++) {
        float xf = ((xmask >> m) & 1u) ? 1.0f : 0.0f;
        __stcs(&out[(size_t)(rowBase + m) * Dm + d], xf);
        __stcs(&out[(size_t)Bm * Dm + (size_t)(rowBase + m) * Dm + d], xa[m]);
    }
}

extern "C" void kernel_launch(void* const* d_in, const int* in_sizes, int n_in,
                              void* d_out, int out_size) {
    const float* x  = (const float*)d_in[0];
    const float* xa = (const float*)d_in[1];
    const float* W  = (const float*)d_in[2];
    const float* b  = (const float*)d_in[3];
    const float* rr = (const float*)d_in[4];
    const float* nz = (const float*)d_in[5];
    const float* au = (const float*)d_in[6];
    els_kernel<<<Bm / Mrows, 256>>>(x, xa, W, b, rr, nz, au, (float*)d_out);
}